// round 5
// baseline (speedup 1.0000x reference)
#include <cuda_runtime.h>
#include <math.h>

#define N_NODES 100000
#define C 128
#define BN_EPS 1e-5f
#define MAX_E 1600000
#define SCAN_B 512
#define SCAN_NB ((N_NODES + SCAN_B - 1) / SCAN_B)   // 196

// ---------------- persistent device scratch (no allocations; 16B-aligned) ----------------
__device__ float4 g_agg4[(size_t)N_NODES * C / 4];   // mean-aggregated features
__device__ float4 g_h0_4[(size_t)N_NODES * C / 4];   // layer ping
__device__ float4 g_h1_4[(size_t)N_NODES * C / 4];   // layer pong
__device__ int    g_deg[N_NODES];
__device__ int    g_rowptr[N_NODES + 1];
__device__ int    g_cursor[N_NODES];
__device__ float  g_inv[N_NODES];
__device__ int    g_esrc[MAX_E];
__device__ int    g_boff[SCAN_NB + 1];
__device__ int    g_is64;

// ---------------- detect edge_index dtype (int64 vs int32) ----------------
__global__ void detect_kernel(const void* __restrict__ ei) {
    const long long* p64 = (const long long*)ei;
    int ok = 1;
    for (int i = 0; i < 64; ++i) {
        long long v = p64[i];
        if (v < 0 || v >= N_NODES) { ok = 0; break; }
    }
    g_is64 = ok;
}

__device__ __forceinline__ int load_idx(const void* ei, size_t i) {
    return g_is64 ? (int)((const long long*)ei)[i] : ((const int*)ei)[i];
}

// ---------------- CSR build ----------------
__global__ void zero_deg_kernel() {
    int i = blockIdx.x * blockDim.x + threadIdx.x;
    if (i < N_NODES) g_deg[i] = 0;
}

__global__ void hist_kernel(const void* __restrict__ ei, int E) {
    int e = blockIdx.x * blockDim.x + threadIdx.x;
    if (e >= E) return;
    int d = load_idx(ei, (size_t)E + e);
    if ((unsigned)d < N_NODES) atomicAdd(&g_deg[d], 1);
}

__global__ void bsum_kernel() {
    __shared__ int sh[SCAN_B];
    int i = blockIdx.x * SCAN_B + threadIdx.x;
    sh[threadIdx.x] = (i < N_NODES) ? g_deg[i] : 0;
    __syncthreads();
    for (int s = SCAN_B / 2; s > 0; s >>= 1) {
        if (threadIdx.x < s) sh[threadIdx.x] += sh[threadIdx.x + s];
        __syncthreads();
    }
    if (threadIdx.x == 0) g_boff[blockIdx.x] = sh[0];
}

__global__ void scan_boff_kernel() {
    if (threadIdx.x == 0 && blockIdx.x == 0) {
        int acc = 0;
        for (int b = 0; b < SCAN_NB; ++b) {
            int v = g_boff[b];
            g_boff[b] = acc;
            acc += v;
        }
        g_boff[SCAN_NB] = acc;
    }
}

__global__ void rowptr_kernel(int E) {
    __shared__ int sh[SCAN_B];
    int i = blockIdx.x * SCAN_B + threadIdx.x;
    int d = (i < N_NODES) ? g_deg[i] : 0;
    sh[threadIdx.x] = d;
    __syncthreads();
    for (int s = 1; s < SCAN_B; s <<= 1) {
        int v = (threadIdx.x >= s) ? sh[threadIdx.x - s] : 0;
        __syncthreads();
        sh[threadIdx.x] += v;
        __syncthreads();
    }
    if (i < N_NODES) {
        int start = g_boff[blockIdx.x] + sh[threadIdx.x] - d;  // exclusive
        g_rowptr[i] = start;
        g_cursor[i] = start;
        g_inv[i] = 1.0f / fmaxf((float)d, 1.0f);
        if (i == N_NODES - 1) g_rowptr[N_NODES] = g_boff[SCAN_NB];
    }
}

__global__ void fill_kernel(const void* __restrict__ ei, int E) {
    int e = blockIdx.x * blockDim.x + threadIdx.x;
    if (e >= E) return;
    int s = load_idx(ei, e);
    int d = load_idx(ei, (size_t)E + e);
    if ((unsigned)s >= N_NODES || (unsigned)d >= N_NODES) return;
    int slot = atomicAdd(&g_cursor[d], 1);
    if (slot < MAX_E) g_esrc[slot] = s;
}

// ---------------- gather-aggregate: warp per node, writes mean directly ----------------
__global__ __launch_bounds__(256)
void gather_kernel(const float4* __restrict__ x_ext, int in_sel) {
    const float4* x = (in_sel == 0) ? x_ext : (in_sel == 1 ? g_h0_4 : g_h1_4);
    int warp = (blockIdx.x * blockDim.x + threadIdx.x) >> 5;
    int lane = threadIdx.x & 31;
    if (warp >= N_NODES) return;
    int beg = g_rowptr[warp];
    int end = g_rowptr[warp + 1];

    float4 a0 = make_float4(0.f, 0.f, 0.f, 0.f);
    float4 a1 = a0, a2 = a0, a3 = a0;
    int e = beg;
    for (; e + 4 <= end; e += 4) {
        int s0 = g_esrc[e], s1 = g_esrc[e + 1], s2 = g_esrc[e + 2], s3 = g_esrc[e + 3];
        float4 v0 = x[(size_t)s0 * 32 + lane];
        float4 v1 = x[(size_t)s1 * 32 + lane];
        float4 v2 = x[(size_t)s2 * 32 + lane];
        float4 v3 = x[(size_t)s3 * 32 + lane];
        a0.x += v0.x; a0.y += v0.y; a0.z += v0.z; a0.w += v0.w;
        a1.x += v1.x; a1.y += v1.y; a1.z += v1.z; a1.w += v1.w;
        a2.x += v2.x; a2.y += v2.y; a2.z += v2.z; a2.w += v2.w;
        a3.x += v3.x; a3.y += v3.y; a3.z += v3.z; a3.w += v3.w;
    }
    for (; e < end; ++e) {
        int s0 = g_esrc[e];
        float4 v0 = x[(size_t)s0 * 32 + lane];
        a0.x += v0.x; a0.y += v0.y; a0.z += v0.z; a0.w += v0.w;
    }
    a0.x += a1.x + a2.x + a3.x;
    a0.y += a1.y + a2.y + a3.y;
    a0.z += a1.z + a2.z + a3.z;
    a0.w += a1.w + a2.w + a3.w;
    float iv = g_inv[warp];
    a0.x *= iv; a0.y *= iv; a0.z *= iv; a0.w *= iv;
    g_agg4[(size_t)warp * 32 + lane] = a0;
}

// ---------------- fused pipelined GEMM: out = mean @ Wl + bl + hin @ Wr, BN (+ Mish) -----
// CTA: 256 threads, 128x128 tile, K=256 in 16 chunks of 16, double-buffered smem,
// register prefetch of chunk k+1 overlapped with compute of chunk k. One barrier/chunk.
__global__ __launch_bounds__(256)
void sage_gemm_kernel(const float* __restrict__ hin_ext, int in_sel,
                      float* __restrict__ out_ext, int out_sel,
                      const float* __restrict__ Wl, const float* __restrict__ bl,
                      const float* __restrict__ Wr,
                      const float* __restrict__ gamma, const float* __restrict__ beta,
                      const float* __restrict__ rmean, const float* __restrict__ rvar,
                      int apply_mish) {
    const float* hin = (in_sel == 0) ? hin_ext : (in_sel == 1 ? (const float*)g_h0_4
                                                              : (const float*)g_h1_4);
    float* out = (out_sel == 0) ? out_ext : (out_sel == 1 ? (float*)g_h0_4
                                                          : (float*)g_h1_4);

    __shared__ float As[2][128 * 16];
    __shared__ float Bs[2][16 * 128];
    __shared__ float s_sc[128];
    __shared__ float s_off[128];

    int t = threadIdx.x;
    int row0 = blockIdx.x * 128;

    if (t < 128) {
        float sc = gamma[t] * rsqrtf(rvar[t] + BN_EPS);
        s_sc[t] = sc;
        s_off[t] = (bl[t] - rmean[t]) * sc + beta[t];
    }

    int tx = t & 15;   // col group: cols tx*8 .. tx*8+7
    int ty = t >> 4;   // row group: rows ty*8 .. ty*8+7

    float acc[8][8];
#pragma unroll
    for (int i = 0; i < 8; ++i)
#pragma unroll
        for (int j = 0; j < 8; ++j) acc[i][j] = 0.f;

    int a_m = t >> 2;   // 0..63 (and +64)
    int a_c = t & 3;    // float4 column within 16-wide k chunk
    int b_k = t >> 5;   // 0..7 (and +8)
    int b_c = t & 31;   // float4 column within 128-wide row

    // ---- load K-chunk `kt` into registers ----
    auto ldg_tile = [&](int kt, float4 pa[2], float4 pb[2]) {
        int kc = kt * 16;
        bool isAgg = (kc < C);
        const float* Abase = isAgg ? (const float*)g_agg4 : hin;
        const float* Wb    = isAgg ? Wl : Wr;
        int koff = isAgg ? kc : (kc - C);
#pragma unroll
        for (int h = 0; h < 2; ++h) {
            int r = row0 + a_m + h * 64;
            pa[h] = (r < N_NODES)
                  ? *(const float4*)(Abase + (size_t)r * C + koff + a_c * 4)
                  : make_float4(0.f, 0.f, 0.f, 0.f);
        }
#pragma unroll
        for (int h = 0; h < 2; ++h) {
            int k = b_k + h * 8;
            pb[h] = *(const float4*)(Wb + (size_t)(koff + k) * C + b_c * 4);
        }
    };
    auto sts_tile = [&](int buf, const float4 pa[2], const float4 pb[2]) {
#pragma unroll
        for (int h = 0; h < 2; ++h)
            *(float4*)(&As[buf][(a_m + h * 64) * 16 + a_c * 4]) = pa[h];
#pragma unroll
        for (int h = 0; h < 2; ++h)
            *(float4*)(&Bs[buf][(b_k + h * 8) * 128 + b_c * 4]) = pb[h];
    };

    // prologue: chunk 0 -> buffer 0
    {
        float4 pa[2], pb[2];
        ldg_tile(0, pa, pb);
        sts_tile(0, pa, pb);
    }
    __syncthreads();

    for (int kt = 0; kt < 16; ++kt) {
        int cur = kt & 1;
        float4 pa[2], pb[2];
        bool have_next = (kt + 1 < 16);
        if (have_next) ldg_tile(kt + 1, pa, pb);   // overlap with compute below

#pragma unroll
        for (int kk4 = 0; kk4 < 4; ++kk4) {
            float4 a[8];
#pragma unroll
            for (int i = 0; i < 8; ++i)
                a[i] = *(const float4*)(&As[cur][(ty * 8 + i) * 16 + kk4 * 4]);
#pragma unroll
            for (int q = 0; q < 4; ++q) {
                int kk = kk4 * 4 + q;
                float4 b0 = *(const float4*)(&Bs[cur][kk * 128 + tx * 8]);
                float4 b1 = *(const float4*)(&Bs[cur][kk * 128 + tx * 8 + 4]);
#pragma unroll
                for (int i = 0; i < 8; ++i) {
                    float av = (q == 0) ? a[i].x : (q == 1) ? a[i].y
                             : (q == 2) ? a[i].z : a[i].w;
                    acc[i][0] += av * b0.x; acc[i][1] += av * b0.y;
                    acc[i][2] += av * b0.z; acc[i][3] += av * b0.w;
                    acc[i][4] += av * b1.x; acc[i][5] += av * b1.y;
                    acc[i][6] += av * b1.z; acc[i][7] += av * b1.w;
                }
            }
        }

        if (have_next) {
            sts_tile(cur ^ 1, pa, pb);
            __syncthreads();   // everyone done computing `cur` (barrier also orders STS)
        }
    }

    // epilogue: affine-folded BN (+ optional Mish), vectorized stores
#pragma unroll
    for (int i = 0; i < 8; ++i) {
        int r = row0 + ty * 8 + i;
        if (r >= N_NODES) continue;
#pragma unroll
        for (int j4 = 0; j4 < 2; ++j4) {
            float4 o;
            float* op = &o.x;
#pragma unroll
            for (int q = 0; q < 4; ++q) {
                int c = tx * 8 + j4 * 4 + q;
                float v = acc[i][j4 * 4 + q] * s_sc[c] + s_off[c];
                if (apply_mish) {
                    float sp = (v > 20.f) ? v : log1pf(expf(v));
                    v = v * tanhf(sp);
                }
                op[q] = v;
            }
            *(float4*)(out + (size_t)r * C + tx * 8 + j4 * 4) = o;
        }
    }
}

// ---------------- host launcher (graph-capturable: kernel launches only) ----------------
extern "C" void kernel_launch(void* const* d_in, const int* in_sizes, int n_in,
                              void* d_out, int out_size) {
    const float* x  = (const float*)d_in[0];
    const void*  ei = d_in[1];
    const float* Wl = (const float*)d_in[2];
    const float* bl = (const float*)d_in[3];
    const float* Wr = (const float*)d_in[4];
    const float* ga = (const float*)d_in[5];
    const float* be = (const float*)d_in[6];
    const float* rm = (const float*)d_in[7];
    const float* rv = (const float*)d_in[8];
    float* out = (float*)d_out;

    int E = in_sizes[1] / 2;

    int eb = (E + 255) / 256;
    int nb = (N_NODES + 255) / 256;
    int wb = (N_NODES * 32 + 255) / 256;   // warp-per-node gather
    int gb = (N_NODES + 127) / 128;

    // ---- CSR build (once per launch; dst shared by all 3 layers) ----
    detect_kernel<<<1, 1>>>(ei);
    zero_deg_kernel<<<nb, 256>>>();
    hist_kernel<<<eb, 256>>>(ei, E);
    bsum_kernel<<<SCAN_NB, SCAN_B>>>();
    scan_boff_kernel<<<1, 32>>>();
    rowptr_kernel<<<SCAN_NB, SCAN_B>>>(E);
    fill_kernel<<<eb, 256>>>(ei, E);

    // layer 0: in = x, out = g_h0
    gather_kernel<<<wb, 256>>>((const float4*)x, 0);
    sage_gemm_kernel<<<gb, 256>>>(x, 0, nullptr, 1,
                                  Wl + 0 * C * C, bl + 0 * C, Wr + 0 * C * C,
                                  ga + 0 * C, be + 0 * C, rm + 0 * C, rv + 0 * C, 1);

    // layer 1: in = g_h0, out = g_h1
    gather_kernel<<<wb, 256>>>(nullptr, 1);
    sage_gemm_kernel<<<gb, 256>>>(nullptr, 1, nullptr, 2,
                                  Wl + 1 * C * C, bl + 1 * C, Wr + 1 * C * C,
                                  ga + 1 * C, be + 1 * C, rm + 1 * C, rv + 1 * C, 1);

    // layer 2: in = g_h1, out = d_out, no Mish
    gather_kernel<<<wb, 256>>>(nullptr, 2);
    sage_gemm_kernel<<<gb, 256>>>(nullptr, 2, out, 0,
                                  Wl + 2 * C * C, bl + 2 * C, Wr + 2 * C * C,
                                  ga + 2 * C, be + 2 * C, rm + 2 * C, rv + 2 * C, 0);
}

// round 6
// speedup vs baseline: 1.1531x; 1.1531x over previous
#include <cuda_runtime.h>
#include <math.h>
#include <stdint.h>

#define N_NODES 100000
#define C 128
#define BN_EPS 1e-5f
#define MAX_E 1600000
#define SCAN_B 512
#define SCAN_NB ((N_NODES + SCAN_B - 1) / SCAN_B)   // 196

// ---------------- persistent device scratch (no allocations; 16B-aligned) ----------------
__device__ float4 g_agg4[(size_t)N_NODES * C / 4];   // mean-aggregated features
__device__ float4 g_h0_4[(size_t)N_NODES * C / 4];   // layer ping
__device__ float4 g_h1_4[(size_t)N_NODES * C / 4];   // layer pong
__device__ int    g_deg[N_NODES];
__device__ int    g_rowptr[N_NODES + 1];
__device__ int    g_cursor[N_NODES];
__device__ float  g_inv[N_NODES];
__device__ int    g_esrc[MAX_E];
__device__ int    g_boff[SCAN_NB + 1];
__device__ int    g_is64;

// ---------------- detect edge_index dtype (int64 vs int32) ----------------
__global__ void detect_kernel(const void* __restrict__ ei) {
    const long long* p64 = (const long long*)ei;
    int ok = 1;
    for (int i = 0; i < 64; ++i) {
        long long v = p64[i];
        if (v < 0 || v >= N_NODES) { ok = 0; break; }
    }
    g_is64 = ok;
}

__device__ __forceinline__ int load_idx(const void* ei, size_t i) {
    return g_is64 ? (int)((const long long*)ei)[i] : ((const int*)ei)[i];
}

// ---------------- CSR build ----------------
__global__ void zero_deg_kernel() {
    int i = blockIdx.x * blockDim.x + threadIdx.x;
    if (i < N_NODES) g_deg[i] = 0;
}

__global__ void hist_kernel(const void* __restrict__ ei, int E) {
    int e = blockIdx.x * blockDim.x + threadIdx.x;
    if (e >= E) return;
    int d = load_idx(ei, (size_t)E + e);
    if ((unsigned)d < N_NODES) atomicAdd(&g_deg[d], 1);
}

__global__ void bsum_kernel() {
    __shared__ int sh[SCAN_B];
    int i = blockIdx.x * SCAN_B + threadIdx.x;
    sh[threadIdx.x] = (i < N_NODES) ? g_deg[i] : 0;
    __syncthreads();
    for (int s = SCAN_B / 2; s > 0; s >>= 1) {
        if (threadIdx.x < s) sh[threadIdx.x] += sh[threadIdx.x + s];
        __syncthreads();
    }
    if (threadIdx.x == 0) g_boff[blockIdx.x] = sh[0];
}

__global__ void scan_boff_kernel() {
    if (threadIdx.x == 0 && blockIdx.x == 0) {
        int acc = 0;
        for (int b = 0; b < SCAN_NB; ++b) {
            int v = g_boff[b];
            g_boff[b] = acc;
            acc += v;
        }
        g_boff[SCAN_NB] = acc;
    }
}

__global__ void rowptr_kernel(int E) {
    __shared__ int sh[SCAN_B];
    int i = blockIdx.x * SCAN_B + threadIdx.x;
    int d = (i < N_NODES) ? g_deg[i] : 0;
    sh[threadIdx.x] = d;
    __syncthreads();
    for (int s = 1; s < SCAN_B; s <<= 1) {
        int v = (threadIdx.x >= s) ? sh[threadIdx.x - s] : 0;
        __syncthreads();
        sh[threadIdx.x] += v;
        __syncthreads();
    }
    if (i < N_NODES) {
        int start = g_boff[blockIdx.x] + sh[threadIdx.x] - d;  // exclusive
        g_rowptr[i] = start;
        g_cursor[i] = start;
        g_inv[i] = 1.0f / fmaxf((float)d, 1.0f);
        if (i == N_NODES - 1) g_rowptr[N_NODES] = g_boff[SCAN_NB];
    }
}

__global__ void fill_kernel(const void* __restrict__ ei, int E) {
    int e = blockIdx.x * blockDim.x + threadIdx.x;
    if (e >= E) return;
    int s = load_idx(ei, e);
    int d = load_idx(ei, (size_t)E + e);
    if ((unsigned)s >= N_NODES || (unsigned)d >= N_NODES) return;
    int slot = atomicAdd(&g_cursor[d], 1);
    if (slot < MAX_E) g_esrc[slot] = s;
}

// ---------------- gather-aggregate: warp per node, writes mean directly ----------------
__global__ __launch_bounds__(256)
void gather_kernel(const float4* __restrict__ x_ext, int in_sel) {
    const float4* x = (in_sel == 0) ? x_ext : (in_sel == 1 ? g_h0_4 : g_h1_4);
    int warp = (blockIdx.x * blockDim.x + threadIdx.x) >> 5;
    int lane = threadIdx.x & 31;
    if (warp >= N_NODES) return;
    int beg = g_rowptr[warp];
    int end = g_rowptr[warp + 1];

    float4 a0 = make_float4(0.f, 0.f, 0.f, 0.f);
    float4 a1 = a0, a2 = a0, a3 = a0;
    int e = beg;
    for (; e + 4 <= end; e += 4) {
        int s0 = g_esrc[e], s1 = g_esrc[e + 1], s2 = g_esrc[e + 2], s3 = g_esrc[e + 3];
        float4 v0 = x[(size_t)s0 * 32 + lane];
        float4 v1 = x[(size_t)s1 * 32 + lane];
        float4 v2 = x[(size_t)s2 * 32 + lane];
        float4 v3 = x[(size_t)s3 * 32 + lane];
        a0.x += v0.x; a0.y += v0.y; a0.z += v0.z; a0.w += v0.w;
        a1.x += v1.x; a1.y += v1.y; a1.z += v1.z; a1.w += v1.w;
        a2.x += v2.x; a2.y += v2.y; a2.z += v2.z; a2.w += v2.w;
        a3.x += v3.x; a3.y += v3.y; a3.z += v3.z; a3.w += v3.w;
    }
    for (; e < end; ++e) {
        int s0 = g_esrc[e];
        float4 v0 = x[(size_t)s0 * 32 + lane];
        a0.x += v0.x; a0.y += v0.y; a0.z += v0.z; a0.w += v0.w;
    }
    a0.x += a1.x + a2.x + a3.x;
    a0.y += a1.y + a2.y + a3.y;
    a0.z += a1.z + a2.z + a3.z;
    a0.w += a1.w + a2.w + a3.w;
    float iv = g_inv[warp];
    a0.x *= iv; a0.y *= iv; a0.z *= iv; a0.w *= iv;
    g_agg4[(size_t)warp * 32 + lane] = a0;
}

// ---------------- cp.async helpers ----------------
__device__ __forceinline__ void cp_async16(uint32_t dst_smem, const void* src, int src_bytes) {
    asm volatile("cp.async.cg.shared.global [%0], [%1], 16, %2;\n"
                 :: "r"(dst_smem), "l"(src), "r"(src_bytes));
}
__device__ __forceinline__ void cp_async_commit() {
    asm volatile("cp.async.commit_group;\n");
}
__device__ __forceinline__ void cp_async_wait0() {
    asm volatile("cp.async.wait_group 0;\n");
}

// ---------------- fused pipelined GEMM: out = mean @ Wl + bl + hin @ Wr, BN (+ Mish) -----
// CTA: 256 threads, 128x128 tile, K=256 in 16 chunks of 16. Double-buffered smem with
// cp.async (no register staging): copy chunk k+1 overlaps compute of chunk k.
__global__ __launch_bounds__(256)
void sage_gemm_kernel(const float* __restrict__ hin_ext, int in_sel,
                      float* __restrict__ out_ext, int out_sel,
                      const float* __restrict__ Wl, const float* __restrict__ bl,
                      const float* __restrict__ Wr,
                      const float* __restrict__ gamma, const float* __restrict__ beta,
                      const float* __restrict__ rmean, const float* __restrict__ rvar,
                      int apply_mish) {
    const float* hin = (in_sel == 0) ? hin_ext : (in_sel == 1 ? (const float*)g_h0_4
                                                              : (const float*)g_h1_4);
    float* out = (out_sel == 0) ? out_ext : (out_sel == 1 ? (float*)g_h0_4
                                                          : (float*)g_h1_4);

    __shared__ float As[2][128 * 16];
    __shared__ float Bs[2][16 * 128];
    __shared__ float s_sc[128];
    __shared__ float s_off[128];

    int t = threadIdx.x;
    int row0 = blockIdx.x * 128;

    if (t < 128) {
        float sc = gamma[t] * rsqrtf(rvar[t] + BN_EPS);
        s_sc[t] = sc;
        s_off[t] = (bl[t] - rmean[t]) * sc + beta[t];
    }

    int tx = t & 15;   // col group: cols tx*8 .. tx*8+7
    int ty = t >> 4;   // row group: rows ty*8 .. ty*8+7

    float acc[8][8];
#pragma unroll
    for (int i = 0; i < 8; ++i)
#pragma unroll
        for (int j = 0; j < 8; ++j) acc[i][j] = 0.f;

    int a_m = t >> 2;   // 0..63 (and +64)
    int a_c = t & 3;    // float4 column within 16-wide k chunk
    int b_k = t >> 5;   // 0..7 (and +8)
    int b_c = t & 31;   // float4 column within 128-wide row

    uint32_t As0 = (uint32_t)__cvta_generic_to_shared(&As[0][0]);
    uint32_t Bs0 = (uint32_t)__cvta_generic_to_shared(&Bs[0][0]);

    // issue async copy of K-chunk `kt` into buffer `buf`
    auto cp_tile = [&](int kt, int buf) {
        int kc = kt * 16;
        bool isAgg = (kc < C);
        const float* Abase = isAgg ? (const float*)g_agg4 : hin;
        const float* Wb    = isAgg ? Wl : Wr;
        int koff = isAgg ? kc : (kc - C);
#pragma unroll
        for (int h = 0; h < 2; ++h) {
            int m = a_m + h * 64;
            int r = row0 + m;
            int rc = (r < N_NODES) ? r : 0;          // clamp addr; zero-fill via src_bytes
            cp_async16(As0 + (uint32_t)(buf * 8192 + (m * 16 + a_c * 4) * 4),
                       Abase + (size_t)rc * C + koff + a_c * 4,
                       (r < N_NODES) ? 16 : 0);
        }
#pragma unroll
        for (int h = 0; h < 2; ++h) {
            int k = b_k + h * 8;
            cp_async16(Bs0 + (uint32_t)(buf * 8192 + (k * 128 + b_c * 4) * 4),
                       Wb + (size_t)(koff + k) * C + b_c * 4, 16);
        }
        cp_async_commit();
    };

    // prologue: chunk 0 -> buffer 0
    cp_tile(0, 0);
    cp_async_wait0();
    __syncthreads();

    for (int kt = 0; kt < 16; ++kt) {
        int cur = kt & 1;
        bool have_next = (kt + 1 < 16);
        if (have_next) cp_tile(kt + 1, cur ^ 1);   // async, overlaps compute below

#pragma unroll
        for (int kk4 = 0; kk4 < 4; ++kk4) {
            float4 a[8];
#pragma unroll
            for (int i = 0; i < 8; ++i)
                a[i] = *(const float4*)(&As[cur][(ty * 8 + i) * 16 + kk4 * 4]);
#pragma unroll
            for (int q = 0; q < 4; ++q) {
                int kk = kk4 * 4 + q;
                float4 b0 = *(const float4*)(&Bs[cur][kk * 128 + tx * 8]);
                float4 b1 = *(const float4*)(&Bs[cur][kk * 128 + tx * 8 + 4]);
#pragma unroll
                for (int i = 0; i < 8; ++i) {
                    float av = (q == 0) ? a[i].x : (q == 1) ? a[i].y
                             : (q == 2) ? a[i].z : a[i].w;
                    acc[i][0] += av * b0.x; acc[i][1] += av * b0.y;
                    acc[i][2] += av * b0.z; acc[i][3] += av * b0.w;
                    acc[i][4] += av * b1.x; acc[i][5] += av * b1.y;
                    acc[i][6] += av * b1.z; acc[i][7] += av * b1.w;
                }
            }
        }

        if (have_next) {
            cp_async_wait0();
            __syncthreads();   // copies landed; all readers of next buffer done
        }
    }

    // epilogue: affine-folded BN (+ optional Mish), vectorized stores
#pragma unroll
    for (int i = 0; i < 8; ++i) {
        int r = row0 + ty * 8 + i;
        if (r >= N_NODES) continue;
#pragma unroll
        for (int j4 = 0; j4 < 2; ++j4) {
            float4 o;
            float* op = &o.x;
#pragma unroll
            for (int q = 0; q < 4; ++q) {
                int c = tx * 8 + j4 * 4 + q;
                float v = acc[i][j4 * 4 + q] * s_sc[c] + s_off[c];
                if (apply_mish) {
                    float sp = (v > 20.f) ? v : log1pf(expf(v));
                    v = v * tanhf(sp);
                }
                op[q] = v;
            }
            *(float4*)(out + (size_t)r * C + tx * 8 + j4 * 4) = o;
        }
    }
}

// ---------------- host launcher (graph-capturable: kernel launches only) ----------------
extern "C" void kernel_launch(void* const* d_in, const int* in_sizes, int n_in,
                              void* d_out, int out_size) {
    const float* x  = (const float*)d_in[0];
    const void*  ei = d_in[1];
    const float* Wl = (const float*)d_in[2];
    const float* bl = (const float*)d_in[3];
    const float* Wr = (const float*)d_in[4];
    const float* ga = (const float*)d_in[5];
    const float* be = (const float*)d_in[6];
    const float* rm = (const float*)d_in[7];
    const float* rv = (const float*)d_in[8];
    float* out = (float*)d_out;

    int E = in_sizes[1] / 2;

    int eb = (E + 255) / 256;
    int nb = (N_NODES + 255) / 256;
    int wb = (N_NODES * 32 + 255) / 256;   // warp-per-node gather
    int gb = (N_NODES + 127) / 128;

    // ---- CSR build (once per launch; dst shared by all 3 layers) ----
    detect_kernel<<<1, 1>>>(ei);
    zero_deg_kernel<<<nb, 256>>>();
    hist_kernel<<<eb, 256>>>(ei, E);
    bsum_kernel<<<SCAN_NB, SCAN_B>>>();
    scan_boff_kernel<<<1, 32>>>();
    rowptr_kernel<<<SCAN_NB, SCAN_B>>>(E);
    fill_kernel<<<eb, 256>>>(ei, E);

    // layer 0: in = x, out = g_h0
    gather_kernel<<<wb, 256>>>((const float4*)x, 0);
    sage_gemm_kernel<<<gb, 256>>>(x, 0, nullptr, 1,
                                  Wl + 0 * C * C, bl + 0 * C, Wr + 0 * C * C,
                                  ga + 0 * C, be + 0 * C, rm + 0 * C, rv + 0 * C, 1);

    // layer 1: in = g_h0, out = g_h1
    gather_kernel<<<wb, 256>>>(nullptr, 1);
    sage_gemm_kernel<<<gb, 256>>>(nullptr, 1, nullptr, 2,
                                  Wl + 1 * C * C, bl + 1 * C, Wr + 1 * C * C,
                                  ga + 1 * C, be + 1 * C, rm + 1 * C, rv + 1 * C, 1);

    // layer 2: in = g_h1, out = d_out, no Mish
    gather_kernel<<<wb, 256>>>(nullptr, 2);
    sage_gemm_kernel<<<gb, 256>>>(nullptr, 2, out, 0,
                                  Wl + 2 * C * C, bl + 2 * C, Wr + 2 * C * C,
                                  ga + 2 * C, be + 2 * C, rm + 2 * C, rv + 2 * C, 0);
}

// round 10
// speedup vs baseline: 1.4087x; 1.2216x over previous
#include <cuda_runtime.h>
#include <cuda_bf16.h>
#include <math.h>
#include <stdint.h>

#define N_NODES 100000
#define C 128
#define BN_EPS 1e-5f
#define MAX_E 1600000
#define SCAN_B 512
#define SCAN_NB ((N_NODES + SCAN_B - 1) / SCAN_B)   // 196

// ---------------- persistent device scratch (no allocations; 16B-aligned) ----------------
__device__ float4 g_agg4[(size_t)N_NODES * C / 4];   // mean-aggregated features
__device__ float4 g_h0_4[(size_t)N_NODES * C / 4];   // layer ping
__device__ float4 g_h1_4[(size_t)N_NODES * C / 4];   // layer pong
__device__ int    g_deg[N_NODES];
__device__ int    g_rowptr[N_NODES + 1];
__device__ int    g_cursor[N_NODES];
__device__ float  g_inv[N_NODES];
__device__ int    g_esrc[MAX_E];
__device__ int    g_boff[SCAN_NB + 1];
__device__ int    g_is64;

// ---------------- warp-MMA helpers (sm_80+ PTX: valid under sm_100 target) ---------------
__device__ __forceinline__ uint32_t smem_u32(const void* p) {
    return (uint32_t)__cvta_generic_to_shared(p);
}
__device__ __forceinline__ void ldmx4(uint32_t r[4], uint32_t addr) {
    asm volatile("ldmatrix.sync.aligned.m8n8.x4.shared.b16 {%0,%1,%2,%3}, [%4];"
                 : "=r"(r[0]), "=r"(r[1]), "=r"(r[2]), "=r"(r[3]) : "r"(addr));
}
__device__ __forceinline__ void ldmx4t(uint32_t r[4], uint32_t addr) {
    asm volatile("ldmatrix.sync.aligned.m8n8.x4.trans.shared.b16 {%0,%1,%2,%3}, [%4];"
                 : "=r"(r[0]), "=r"(r[1]), "=r"(r[2]), "=r"(r[3]) : "r"(addr));
}
__device__ __forceinline__ void mma16816(float c[4], const uint32_t a[4], const uint32_t b[2]) {
    asm volatile("mma.sync.aligned.m16n8k16.row.col.f32.bf16.bf16.f32 "
                 "{%0,%1,%2,%3}, {%4,%5,%6,%7}, {%8,%9}, {%0,%1,%2,%3};"
                 : "+f"(c[0]), "+f"(c[1]), "+f"(c[2]), "+f"(c[3])
                 : "r"(a[0]), "r"(a[1]), "r"(a[2]), "r"(a[3]), "r"(b[0]), "r"(b[1]));
}

// ---------------- detect edge_index dtype (int64 vs int32) ----------------
__global__ void detect_kernel(const void* __restrict__ ei) {
    const long long* p64 = (const long long*)ei;
    int ok = 1;
    for (int i = 0; i < 64; ++i) {
        long long v = p64[i];
        if (v < 0 || v >= N_NODES) { ok = 0; break; }
    }
    g_is64 = ok;
}

__device__ __forceinline__ int load_idx(const void* ei, size_t i) {
    return g_is64 ? (int)((const long long*)ei)[i] : ((const int*)ei)[i];
}

// ---------------- CSR build ----------------
__global__ void zero_deg_kernel() {
    int i = blockIdx.x * blockDim.x + threadIdx.x;
    if (i < N_NODES) g_deg[i] = 0;
}

__global__ void hist_kernel(const void* __restrict__ ei, int E) {
    int e = blockIdx.x * blockDim.x + threadIdx.x;
    if (e >= E) return;
    int d = load_idx(ei, (size_t)E + e);
    if ((unsigned)d < N_NODES) atomicAdd(&g_deg[d], 1);
}

__global__ void bsum_kernel() {
    __shared__ int sh[SCAN_B];
    int i = blockIdx.x * SCAN_B + threadIdx.x;
    sh[threadIdx.x] = (i < N_NODES) ? g_deg[i] : 0;
    __syncthreads();
    for (int s = SCAN_B / 2; s > 0; s >>= 1) {
        if (threadIdx.x < s) sh[threadIdx.x] += sh[threadIdx.x + s];
        __syncthreads();
    }
    if (threadIdx.x == 0) g_boff[blockIdx.x] = sh[0];
}

__global__ void scan_boff_kernel() {
    if (threadIdx.x == 0 && blockIdx.x == 0) {
        int acc = 0;
        for (int b = 0; b < SCAN_NB; ++b) {
            int v = g_boff[b];
            g_boff[b] = acc;
            acc += v;
        }
        g_boff[SCAN_NB] = acc;
    }
}

__global__ void rowptr_kernel(int E) {
    __shared__ int sh[SCAN_B];
    int i = blockIdx.x * SCAN_B + threadIdx.x;
    int d = (i < N_NODES) ? g_deg[i] : 0;
    sh[threadIdx.x] = d;
    __syncthreads();
    for (int s = 1; s < SCAN_B; s <<= 1) {
        int v = (threadIdx.x >= s) ? sh[threadIdx.x - s] : 0;
        __syncthreads();
        sh[threadIdx.x] += v;
        __syncthreads();
    }
    if (i < N_NODES) {
        int start = g_boff[blockIdx.x] + sh[threadIdx.x] - d;  // exclusive
        g_rowptr[i] = start;
        g_cursor[i] = start;
        g_inv[i] = 1.0f / fmaxf((float)d, 1.0f);
        if (i == N_NODES - 1) g_rowptr[N_NODES] = g_boff[SCAN_NB];
    }
}

__global__ void fill_kernel(const void* __restrict__ ei, int E) {
    int e = blockIdx.x * blockDim.x + threadIdx.x;
    if (e >= E) return;
    int s = load_idx(ei, e);
    int d = load_idx(ei, (size_t)E + e);
    if ((unsigned)s >= N_NODES || (unsigned)d >= N_NODES) return;
    int slot = atomicAdd(&g_cursor[d], 1);
    if (slot < MAX_E) g_esrc[slot] = s;
}

// ---------------- gather-aggregate: warp per node, writes mean directly ----------------
__global__ __launch_bounds__(256)
void gather_kernel(const float4* __restrict__ x_ext, int in_sel) {
    const float4* x = (in_sel == 0) ? x_ext : (in_sel == 1 ? g_h0_4 : g_h1_4);
    int warp = (blockIdx.x * blockDim.x + threadIdx.x) >> 5;
    int lane = threadIdx.x & 31;
    if (warp >= N_NODES) return;
    int beg = g_rowptr[warp];
    int end = g_rowptr[warp + 1];

    float4 a0 = make_float4(0.f, 0.f, 0.f, 0.f);
    float4 a1 = a0, a2 = a0, a3 = a0;
    int e = beg;
    for (; e + 4 <= end; e += 4) {
        int s0 = g_esrc[e], s1 = g_esrc[e + 1], s2 = g_esrc[e + 2], s3 = g_esrc[e + 3];
        float4 v0 = x[(size_t)s0 * 32 + lane];
        float4 v1 = x[(size_t)s1 * 32 + lane];
        float4 v2 = x[(size_t)s2 * 32 + lane];
        float4 v3 = x[(size_t)s3 * 32 + lane];
        a0.x += v0.x; a0.y += v0.y; a0.z += v0.z; a0.w += v0.w;
        a1.x += v1.x; a1.y += v1.y; a1.z += v1.z; a1.w += v1.w;
        a2.x += v2.x; a2.y += v2.y; a2.z += v2.z; a2.w += v2.w;
        a3.x += v3.x; a3.y += v3.y; a3.z += v3.z; a3.w += v3.w;
    }
    for (; e < end; ++e) {
        int s0 = g_esrc[e];
        float4 v0 = x[(size_t)s0 * 32 + lane];
        a0.x += v0.x; a0.y += v0.y; a0.z += v0.z; a0.w += v0.w;
    }
    a0.x += a1.x + a2.x + a3.x;
    a0.y += a1.y + a2.y + a3.y;
    a0.z += a1.z + a2.z + a3.z;
    a0.w += a1.w + a2.w + a3.w;
    float iv = g_inv[warp];
    a0.x *= iv; a0.y *= iv; a0.z *= iv; a0.w *= iv;
    g_agg4[(size_t)warp * 32 + lane] = a0;
}

// ---------------- tensor-core GEMM: out = mean @ Wl + bl + hin @ Wr, BN (+ Mish) ---------
// fp32 via bf16 hi/lo split: D += Ah@Wh + Ah@Wl + Al@Wh  (fp32 mma.sync accumulators).
// CTA 256 thr / 8 warps, 128x128 tile, warp tile 32x64. K=256 in 8 chunks of 32.
#define APAD 40    // A smem row stride (bf16) -> 80B, conflict-free ldmatrix
#define BPAD 136   // B smem row stride (bf16) -> 272B, conflict-free ldmatrix
__global__ __launch_bounds__(256)
void sage_mma_kernel(const float* __restrict__ hin_ext, int in_sel,
                     float* __restrict__ out_ext, int out_sel,
                     const float* __restrict__ Wl, const float* __restrict__ bl,
                     const float* __restrict__ Wr,
                     const float* __restrict__ gamma, const float* __restrict__ beta,
                     const float* __restrict__ rmean, const float* __restrict__ rvar,
                     int apply_mish) {
    const float* hin = (in_sel == 0) ? hin_ext : (in_sel == 1 ? (const float*)g_h0_4
                                                              : (const float*)g_h1_4);
    float* out = (out_sel == 0) ? out_ext : (out_sel == 1 ? (float*)g_h0_4
                                                          : (float*)g_h1_4);

    __shared__ __align__(16) __nv_bfloat16 sAh[128][APAD];
    __shared__ __align__(16) __nv_bfloat16 sAl[128][APAD];
    __shared__ __align__(16) __nv_bfloat16 sBh[32][BPAD];
    __shared__ __align__(16) __nv_bfloat16 sBl[32][BPAD];
    __shared__ float s_sc[128];
    __shared__ float s_off[128];

    int t = threadIdx.x;
    int wid = t >> 5;
    int lane = t & 31;
    int row0 = blockIdx.x * 128;

    if (t < 128) {
        float sc = gamma[t] * rsqrtf(rvar[t] + BN_EPS);
        s_sc[t] = sc;
        s_off[t] = (bl[t] - rmean[t]) * sc + beta[t];
    }

    int warp_m = wid & 3;          // 4 x 32 rows
    int warp_n = wid >> 2;         // 2 x 64 cols
    int m_base = warp_m * 32;
    int n_base = warp_n * 64;

    float acc[2][8][4];
#pragma unroll
    for (int i = 0; i < 2; ++i)
#pragma unroll
        for (int j = 0; j < 8; ++j)
#pragma unroll
            for (int q = 0; q < 4; ++q) acc[i][j][q] = 0.f;

    // loader indices
    int a_row = t >> 1;            // 0..127
    int a_cg  = (t & 1) * 16;      // 16-col group within 32-wide chunk
    int b_row = t >> 3;            // 0..31 (k)
    int b_cg  = (t & 7) * 16;      // 16-col group within 128-wide row

    // ldmatrix lane addressing (shared by A and B-trans)
    int lg = lane >> 3;            // tile group 0..3
    int lr = lane & 7;
    int frow = lr + (lg & 1) * 8;  // row within 16
    int fcol = (lg >> 1) * 8;      // col offset 0/8

    for (int ck = 0; ck < 8; ++ck) {
        int kc0 = ck * 32;
        bool isAgg = (kc0 < C);
        const float* Abase = isAgg ? (const float*)g_agg4 : hin;
        const float* Wb    = isAgg ? Wl : Wr;
        int koff = isAgg ? kc0 : (kc0 - C);

        if (ck > 0) __syncthreads();   // all warps done reading previous chunk's smem

        // ---- A: 128x32 fp32 -> hi/lo bf16 ----
        {
            int r = row0 + a_row;
            float vv[16];
            if (r < N_NODES) {
                const float* src = Abase + (size_t)r * C + koff + a_cg;
#pragma unroll
                for (int q = 0; q < 4; ++q) {
                    float4 v = *(const float4*)(src + q * 4);
                    vv[q * 4 + 0] = v.x; vv[q * 4 + 1] = v.y;
                    vv[q * 4 + 2] = v.z; vv[q * 4 + 3] = v.w;
                }
            } else {
#pragma unroll
                for (int j = 0; j < 16; ++j) vv[j] = 0.f;
            }
            union { __nv_bfloat16 b[8]; uint4 u; } h0, h1, l0, l1;
#pragma unroll
            for (int j = 0; j < 8; ++j) {
                __nv_bfloat16 h = __float2bfloat16(vv[j]);
                h0.b[j] = h;
                l0.b[j] = __float2bfloat16(vv[j] - __bfloat162float(h));
                __nv_bfloat16 g = __float2bfloat16(vv[8 + j]);
                h1.b[j] = g;
                l1.b[j] = __float2bfloat16(vv[8 + j] - __bfloat162float(g));
            }
            *(uint4*)&sAh[a_row][a_cg]     = h0.u;
            *(uint4*)&sAh[a_row][a_cg + 8] = h1.u;
            *(uint4*)&sAl[a_row][a_cg]     = l0.u;
            *(uint4*)&sAl[a_row][a_cg + 8] = l1.u;
        }
        // ---- B: 32x128 fp32 (W rows koff..koff+31) -> hi/lo bf16 ----
        {
            const float* src = Wb + (size_t)(koff + b_row) * C + b_cg;
            float vv[16];
#pragma unroll
            for (int q = 0; q < 4; ++q) {
                float4 v = *(const float4*)(src + q * 4);
                vv[q * 4 + 0] = v.x; vv[q * 4 + 1] = v.y;
                vv[q * 4 + 2] = v.z; vv[q * 4 + 3] = v.w;
            }
            union { __nv_bfloat16 b[8]; uint4 u; } h0, h1, l0, l1;
#pragma unroll
            for (int j = 0; j < 8; ++j) {
                __nv_bfloat16 h = __float2bfloat16(vv[j]);
                h0.b[j] = h;
                l0.b[j] = __float2bfloat16(vv[j] - __bfloat162float(h));
                __nv_bfloat16 g = __float2bfloat16(vv[8 + j]);
                h1.b[j] = g;
                l1.b[j] = __float2bfloat16(vv[8 + j] - __bfloat162float(g));
            }
            *(uint4*)&sBh[b_row][b_cg]     = h0.u;
            *(uint4*)&sBh[b_row][b_cg + 8] = h1.u;
            *(uint4*)&sBl[b_row][b_cg]     = l0.u;
            *(uint4*)&sBl[b_row][b_cg + 8] = l1.u;
        }
        __syncthreads();

        // ---- compute: 2 k16 steps ----
#pragma unroll
        for (int ks = 0; ks < 2; ++ks) {
            int k0 = ks * 16;
            uint32_t ah[2][4], al[2][4];
#pragma unroll
            for (int mf = 0; mf < 2; ++mf) {
                int ar = m_base + mf * 16 + frow;
                int ac = k0 + fcol;
                ldmx4(ah[mf], smem_u32(&sAh[ar][ac]));
                ldmx4(al[mf], smem_u32(&sAl[ar][ac]));
            }
#pragma unroll
            for (int ng = 0; ng < 4; ++ng) {
                int br = k0 + frow;
                int bc = n_base + ng * 16 + fcol;
                uint32_t bh[4], blo[4];
                ldmx4t(bh,  smem_u32(&sBh[br][bc]));
                ldmx4t(blo, smem_u32(&sBl[br][bc]));
#pragma unroll
                for (int mf = 0; mf < 2; ++mf) {
#pragma unroll
                    for (int h = 0; h < 2; ++h) {
                        float* c = acc[mf][ng * 2 + h];
                        mma16816(c, ah[mf], &bh[h * 2]);
                        mma16816(c, ah[mf], &blo[h * 2]);
                        mma16816(c, al[mf], &bh[h * 2]);
                    }
                }
            }
        }
    }

    // ---- epilogue: BN (+ Mish), float2 stores ----
    int gid = lane >> 2;
    int tig = lane & 3;
#pragma unroll
    for (int mf = 0; mf < 2; ++mf) {
#pragma unroll
        for (int nf = 0; nf < 8; ++nf) {
            int cbase = n_base + nf * 8 + tig * 2;
            float sc0 = s_sc[cbase], sc1 = s_sc[cbase + 1];
            float of0 = s_off[cbase], of1 = s_off[cbase + 1];
#pragma unroll
            for (int h = 0; h < 2; ++h) {
                int r = row0 + m_base + mf * 16 + gid + h * 8;
                if (r >= N_NODES) continue;
                float v0 = acc[mf][nf][h * 2 + 0] * sc0 + of0;
                float v1 = acc[mf][nf][h * 2 + 1] * sc1 + of1;
                if (apply_mish) {
                    float sp0 = (v0 > 20.f) ? v0 : log1pf(expf(v0));
                    v0 = v0 * tanhf(sp0);
                    float sp1 = (v1 > 20.f) ? v1 : log1pf(expf(v1));
                    v1 = v1 * tanhf(sp1);
                }
                float2 o = make_float2(v0, v1);
                *(float2*)(out + (size_t)r * C + cbase) = o;
            }
        }
    }
}

// ---------------- host launcher (graph-capturable: kernel launches only) ----------------
extern "C" void kernel_launch(void* const* d_in, const int* in_sizes, int n_in,
                              void* d_out, int out_size) {
    const float* x  = (const float*)d_in[0];
    const void*  ei = d_in[1];
    const float* Wl = (const float*)d_in[2];
    const float* bl = (const float*)d_in[3];
    const float* Wr = (const float*)d_in[4];
    const float* ga = (const float*)d_in[5];
    const float* be = (const float*)d_in[6];
    const float* rm = (const float*)d_in[7];
    const float* rv = (const float*)d_in[8];
    float* out = (float*)d_out;

    int E = in_sizes[1] / 2;

    int eb = (E + 255) / 256;
    int nb = (N_NODES + 255) / 256;
    int wb = (N_NODES * 32 + 255) / 256;   // warp-per-node gather
    int gb = (N_NODES + 127) / 128;

    // ---- CSR build (once per launch; dst shared by all 3 layers) ----
    detect_kernel<<<1, 1>>>(ei);
    zero_deg_kernel<<<nb, 256>>>();
    hist_kernel<<<eb, 256>>>(ei, E);
    bsum_kernel<<<SCAN_NB, SCAN_B>>>();
    scan_boff_kernel<<<1, 32>>>();
    rowptr_kernel<<<SCAN_NB, SCAN_B>>>(E);
    fill_kernel<<<eb, 256>>>(ei, E);

    // layer 0: in = x, out = g_h0
    gather_kernel<<<wb, 256>>>((const float4*)x, 0);
    sage_mma_kernel<<<gb, 256>>>(x, 0, nullptr, 1,
                                 Wl + 0 * C * C, bl + 0 * C, Wr + 0 * C * C,
                                 ga + 0 * C, be + 0 * C, rm + 0 * C, rv + 0 * C, 1);

    // layer 1: in = g_h0, out = g_h1
    gather_kernel<<<wb, 256>>>(nullptr, 1);
    sage_mma_kernel<<<gb, 256>>>(nullptr, 1, nullptr, 2,
                                 Wl + 1 * C * C, bl + 1 * C, Wr + 1 * C * C,
                                 ga + 1 * C, be + 1 * C, rm + 1 * C, rv + 1 * C, 1);

    // layer 2: in = g_h1, out = d_out, no Mish
    gather_kernel<<<wb, 256>>>(nullptr, 2);
    sage_mma_kernel<<<gb, 256>>>(nullptr, 2, out, 0,
                                 Wl + 2 * C * C, bl + 2 * C, Wr + 2 * C * C,
                                 ga + 2 * C, be + 2 * C, rm + 2 * C, rv + 2 * C, 0);
}

// round 12
// speedup vs baseline: 1.6797x; 1.1924x over previous
#include <cuda_runtime.h>
#include <cuda_bf16.h>
#include <math.h>
#include <stdint.h>

#define N_NODES 100000
#define C 128
#define BN_EPS 1e-5f
#define MAX_E 1600000
#define SCAN_B 512
#define SCAN_NB ((N_NODES + SCAN_B - 1) / SCAN_B)   // 196
#define PLANE4 ((size_t)N_NODES * C / 8)            // uint4 count per bf16 plane

// ---------------- persistent device scratch (no allocations; 16B-aligned) ----------------
// bf16 hi/lo planes (each 25.6 MB)
__device__ uint4 g_agg_h4[PLANE4], g_agg_l4[PLANE4];
__device__ uint4 g_x_h4[PLANE4],   g_x_l4[PLANE4];
__device__ uint4 g_h0_h4[PLANE4],  g_h0_l4[PLANE4];
__device__ uint4 g_h1_h4[PLANE4],  g_h1_l4[PLANE4];
__device__ uint4 g_w_h4[3 * 2 * C * C / 8], g_w_l4[3 * 2 * C * C / 8];  // [layer][k(0..255)][n]
__device__ int    g_deg[N_NODES];
__device__ int    g_rowptr[N_NODES + 1];
__device__ int    g_cursor[N_NODES];
__device__ float  g_inv[N_NODES];
__device__ int    g_esrc[MAX_E];
__device__ int    g_boff[SCAN_NB + 1];
__device__ int    g_is64;

// ---------------- bf16 pack/unpack helpers ----------------
__device__ __forceinline__ float2 bf2f(uint32_t u) {
    return __bfloat1622float2(*reinterpret_cast<const __nv_bfloat162*>(&u));
}
__device__ __forceinline__ uint32_t packbf(__nv_bfloat16 a, __nv_bfloat16 b) {
    __nv_bfloat162 h; h.x = a; h.y = b;
    return *reinterpret_cast<uint32_t*>(&h);
}
// split 2 fp32 -> (hi bf16x2, lo bf16x2)
__device__ __forceinline__ void split2(float v0, float v1, uint32_t& hw, uint32_t& lw) {
    __nv_bfloat16 h0 = __float2bfloat16(v0), h1 = __float2bfloat16(v1);
    __nv_bfloat16 l0 = __float2bfloat16(v0 - __bfloat162float(h0));
    __nv_bfloat16 l1 = __float2bfloat16(v1 - __bfloat162float(h1));
    hw = packbf(h0, h1);
    lw = packbf(l0, l1);
}

// ---------------- warp-MMA helpers (sm_80+ PTX: valid under sm_100 target) ---------------
__device__ __forceinline__ uint32_t smem_u32(const void* p) {
    return (uint32_t)__cvta_generic_to_shared(p);
}
__device__ __forceinline__ void ldmx4(uint32_t r[4], uint32_t addr) {
    asm volatile("ldmatrix.sync.aligned.m8n8.x4.shared.b16 {%0,%1,%2,%3}, [%4];"
                 : "=r"(r[0]), "=r"(r[1]), "=r"(r[2]), "=r"(r[3]) : "r"(addr));
}
__device__ __forceinline__ void ldmx4t(uint32_t r[4], uint32_t addr) {
    asm volatile("ldmatrix.sync.aligned.m8n8.x4.trans.shared.b16 {%0,%1,%2,%3}, [%4];"
                 : "=r"(r[0]), "=r"(r[1]), "=r"(r[2]), "=r"(r[3]) : "r"(addr));
}
__device__ __forceinline__ void mma16816(float c[4], const uint32_t a[4], const uint32_t b[2]) {
    asm volatile("mma.sync.aligned.m16n8k16.row.col.f32.bf16.bf16.f32 "
                 "{%0,%1,%2,%3}, {%4,%5,%6,%7}, {%8,%9}, {%0,%1,%2,%3};"
                 : "+f"(c[0]), "+f"(c[1]), "+f"(c[2]), "+f"(c[3])
                 : "r"(a[0]), "r"(a[1]), "r"(a[2]), "r"(a[3]), "r"(b[0]), "r"(b[1]));
}

// ---------------- detect edge_index dtype (int64 vs int32) ----------------
__global__ void detect_kernel(const void* __restrict__ ei) {
    const long long* p64 = (const long long*)ei;
    int ok = 1;
    for (int i = 0; i < 64; ++i) {
        long long v = p64[i];
        if (v < 0 || v >= N_NODES) { ok = 0; break; }
    }
    g_is64 = ok;
}

__device__ __forceinline__ int load_idx(const void* ei, size_t i) {
    return g_is64 ? (int)((const long long*)ei)[i] : ((const int*)ei)[i];
}

// ---------------- one-time conversions ----------------
__global__ void convw_kernel(const float* __restrict__ Wl, const float* __restrict__ Wr) {
    int i = blockIdx.x * blockDim.x + threadIdx.x;   // over 3*256*128
    if (i >= 3 * 2 * C * C) return;
    int layer = i / (2 * C * C);
    int rem = i % (2 * C * C);
    int k = rem / C, n = rem % C;
    float v = (k < C) ? Wl[(size_t)layer * C * C + k * C + n]
                      : Wr[(size_t)layer * C * C + (k - C) * C + n];
    __nv_bfloat16 h = __float2bfloat16(v);
    ((__nv_bfloat16*)g_w_h4)[i] = h;
    ((__nv_bfloat16*)g_w_l4)[i] = __float2bfloat16(v - __bfloat162float(h));
}

__global__ void convx_kernel(const float4* __restrict__ x4) {
    size_t i = (size_t)blockIdx.x * blockDim.x + threadIdx.x;   // per 4 elements
    if (i >= (size_t)N_NODES * C / 4) return;
    float4 v = x4[i];
    uint2 hw, lw;
    split2(v.x, v.y, hw.x, lw.x);
    split2(v.z, v.w, hw.y, lw.y);
    ((uint2*)g_x_h4)[i] = hw;
    ((uint2*)g_x_l4)[i] = lw;
}

// ---------------- CSR build ----------------
__global__ void zero_deg_kernel() {
    int i = blockIdx.x * blockDim.x + threadIdx.x;
    if (i < N_NODES) g_deg[i] = 0;
}

__global__ void hist_kernel(const void* __restrict__ ei, int E) {
    int e = blockIdx.x * blockDim.x + threadIdx.x;
    if (e >= E) return;
    int d = load_idx(ei, (size_t)E + e);
    if ((unsigned)d < N_NODES) atomicAdd(&g_deg[d], 1);
}

__global__ void bsum_kernel() {
    __shared__ int sh[SCAN_B];
    int i = blockIdx.x * SCAN_B + threadIdx.x;
    sh[threadIdx.x] = (i < N_NODES) ? g_deg[i] : 0;
    __syncthreads();
    for (int s = SCAN_B / 2; s > 0; s >>= 1) {
        if (threadIdx.x < s) sh[threadIdx.x] += sh[threadIdx.x + s];
        __syncthreads();
    }
    if (threadIdx.x == 0) g_boff[blockIdx.x] = sh[0];
}

__global__ void scan_boff_kernel() {
    if (threadIdx.x == 0 && blockIdx.x == 0) {
        int acc = 0;
        for (int b = 0; b < SCAN_NB; ++b) {
            int v = g_boff[b];
            g_boff[b] = acc;
            acc += v;
        }
        g_boff[SCAN_NB] = acc;
    }
}

__global__ void rowptr_kernel(int E) {
    __shared__ int sh[SCAN_B];
    int i = blockIdx.x * SCAN_B + threadIdx.x;
    int d = (i < N_NODES) ? g_deg[i] : 0;
    sh[threadIdx.x] = d;
    __syncthreads();
    for (int s = 1; s < SCAN_B; s <<= 1) {
        int v = (threadIdx.x >= s) ? sh[threadIdx.x - s] : 0;
        __syncthreads();
        sh[threadIdx.x] += v;
        __syncthreads();
    }
    if (i < N_NODES) {
        int start = g_boff[blockIdx.x] + sh[threadIdx.x] - d;  // exclusive
        g_rowptr[i] = start;
        g_cursor[i] = start;
        g_inv[i] = 1.0f / fmaxf((float)d, 1.0f);
        if (i == N_NODES - 1) g_rowptr[N_NODES] = g_boff[SCAN_NB];
    }
}

__global__ void fill_kernel(const void* __restrict__ ei, int E) {
    int e = blockIdx.x * blockDim.x + threadIdx.x;
    if (e >= E) return;
    int s = load_idx(ei, e);
    int d = load_idx(ei, (size_t)E + e);
    if ((unsigned)s >= N_NODES || (unsigned)d >= N_NODES) return;
    int slot = atomicAdd(&g_cursor[d], 1);
    if (slot < MAX_E) g_esrc[slot] = s;
}

// ---------------- gather-aggregate: warp per node; writes mean as bf16 hi/lo planes -----
// in_sel 0: x fp32; 1: h0 planes; 2: h1 planes
__global__ __launch_bounds__(256)
void gather_kernel(const float4* __restrict__ x_ext, int in_sel) {
    int warp = (blockIdx.x * blockDim.x + threadIdx.x) >> 5;
    int lane = threadIdx.x & 31;
    if (warp >= N_NODES) return;
    int beg = g_rowptr[warp];
    int end = g_rowptr[warp + 1];

    float4 a0 = make_float4(0.f, 0.f, 0.f, 0.f);
    float4 a1 = a0;

    if (in_sel == 0) {
        int e = beg;
        for (; e + 2 <= end; e += 2) {
            int s0 = g_esrc[e], s1 = g_esrc[e + 1];
            float4 v0 = x_ext[(size_t)s0 * 32 + lane];
            float4 v1 = x_ext[(size_t)s1 * 32 + lane];
            a0.x += v0.x; a0.y += v0.y; a0.z += v0.z; a0.w += v0.w;
            a1.x += v1.x; a1.y += v1.y; a1.z += v1.z; a1.w += v1.w;
        }
        for (; e < end; ++e) {
            int s0 = g_esrc[e];
            float4 v0 = x_ext[(size_t)s0 * 32 + lane];
            a0.x += v0.x; a0.y += v0.y; a0.z += v0.z; a0.w += v0.w;
        }
    } else {
        const uint2* hp = (in_sel == 1) ? (const uint2*)g_h0_h4 : (const uint2*)g_h1_h4;
        const uint2* lp = (in_sel == 1) ? (const uint2*)g_h0_l4 : (const uint2*)g_h1_l4;
        int e = beg;
        for (; e + 2 <= end; e += 2) {
            int s0 = g_esrc[e], s1 = g_esrc[e + 1];
            uint2 uh0 = hp[(size_t)s0 * 32 + lane];
            uint2 ul0 = lp[(size_t)s0 * 32 + lane];
            uint2 uh1 = hp[(size_t)s1 * 32 + lane];
            uint2 ul1 = lp[(size_t)s1 * 32 + lane];
            float2 h, l;
            h = bf2f(uh0.x); l = bf2f(ul0.x); a0.x += h.x + l.x; a0.y += h.y + l.y;
            h = bf2f(uh0.y); l = bf2f(ul0.y); a0.z += h.x + l.x; a0.w += h.y + l.y;
            h = bf2f(uh1.x); l = bf2f(ul1.x); a1.x += h.x + l.x; a1.y += h.y + l.y;
            h = bf2f(uh1.y); l = bf2f(ul1.y); a1.z += h.x + l.x; a1.w += h.y + l.y;
        }
        for (; e < end; ++e) {
            int s0 = g_esrc[e];
            uint2 uh0 = hp[(size_t)s0 * 32 + lane];
            uint2 ul0 = lp[(size_t)s0 * 32 + lane];
            float2 h, l;
            h = bf2f(uh0.x); l = bf2f(ul0.x); a0.x += h.x + l.x; a0.y += h.y + l.y;
            h = bf2f(uh0.y); l = bf2f(ul0.y); a0.z += h.x + l.x; a0.w += h.y + l.y;
        }
    }
    a0.x += a1.x; a0.y += a1.y; a0.z += a1.z; a0.w += a1.w;
    float iv = g_inv[warp];
    a0.x *= iv; a0.y *= iv; a0.z *= iv; a0.w *= iv;

    uint2 hw, lw;
    split2(a0.x, a0.y, hw.x, lw.x);
    split2(a0.z, a0.w, hw.y, lw.y);
    ((uint2*)g_agg_h4)[(size_t)warp * 32 + lane] = hw;
    ((uint2*)g_agg_l4)[(size_t)warp * 32 + lane] = lw;
}

// ---------------- tensor-core GEMM: pure-copy loader from precomputed bf16 planes --------
// D += Ah@Wh + Ah@Wl + Al@Wh. CTA 256 thr / 8 warps, 128x128 tile, K=256 in 8 chunks of 32.
#define APAD 40
#define BPAD 136
__global__ __launch_bounds__(256)
void sage_mma_kernel(int in_sel, float* __restrict__ out_ext, int out_sel, int layer,
                     const float* __restrict__ bl,
                     const float* __restrict__ gamma, const float* __restrict__ beta,
                     const float* __restrict__ rmean, const float* __restrict__ rvar,
                     int apply_mish) {
    const uint4* hinH = (in_sel == 0) ? g_x_h4 : (in_sel == 1 ? g_h0_h4 : g_h1_h4);
    const uint4* hinL = (in_sel == 0) ? g_x_l4 : (in_sel == 1 ? g_h0_l4 : g_h1_l4);

    __shared__ __align__(16) __nv_bfloat16 sAh[128][APAD];
    __shared__ __align__(16) __nv_bfloat16 sAl[128][APAD];
    __shared__ __align__(16) __nv_bfloat16 sBh[32][BPAD];
    __shared__ __align__(16) __nv_bfloat16 sBl[32][BPAD];
    __shared__ float s_sc[128];
    __shared__ float s_off[128];

    int t = threadIdx.x;
    int wid = t >> 5;
    int lane = t & 31;
    int row0 = blockIdx.x * 128;

    if (t < 128) {
        float sc = gamma[t] * rsqrtf(rvar[t] + BN_EPS);
        s_sc[t] = sc;
        s_off[t] = (bl[t] - rmean[t]) * sc + beta[t];
    }

    int warp_m = wid & 3;
    int warp_n = wid >> 2;
    int m_base = warp_m * 32;
    int n_base = warp_n * 64;

    float acc[2][8][4];
#pragma unroll
    for (int i = 0; i < 2; ++i)
#pragma unroll
        for (int j = 0; j < 8; ++j)
#pragma unroll
            for (int q = 0; q < 4; ++q) acc[i][j][q] = 0.f;

    int a_row = t >> 1;            // 0..127
    int a_cg  = (t & 1) * 16;      // col group (bf16) within 32-wide chunk
    int b_row = t >> 3;            // 0..31 (k)
    int b_cg  = (t & 7) * 16;      // col group within 128-wide row

    const uint4* wH = g_w_h4 + (size_t)layer * (2 * C * C / 8);
    const uint4* wL = g_w_l4 + (size_t)layer * (2 * C * C / 8);

    int lg = lane >> 3;
    int lr = lane & 7;
    int frow = lr + (lg & 1) * 8;
    int fcol = (lg >> 1) * 8;

    for (int ck = 0; ck < 8; ++ck) {
        int kc0 = ck * 32;
        bool isAgg = (kc0 < C);
        const uint4* AH = isAgg ? g_agg_h4 : hinH;
        const uint4* AL = isAgg ? g_agg_l4 : hinL;
        int koff = isAgg ? kc0 : (kc0 - C);

        if (ck > 0) __syncthreads();

        // ---- A: pure 16B copies from planes ----
        {
            int r = row0 + a_row;
            uint4 h0, h1, l0, l1;
            if (r < N_NODES) {
                size_t idx = (size_t)r * 16 + (unsigned)(koff + a_cg) / 8;
                h0 = AH[idx]; h1 = AH[idx + 1];
                l0 = AL[idx]; l1 = AL[idx + 1];
            } else {
                h0 = h1 = l0 = l1 = make_uint4(0, 0, 0, 0);
            }
            *(uint4*)&sAh[a_row][a_cg]     = h0;
            *(uint4*)&sAh[a_row][a_cg + 8] = h1;
            *(uint4*)&sAl[a_row][a_cg]     = l0;
            *(uint4*)&sAl[a_row][a_cg + 8] = l1;
        }
        // ---- B: pure 16B copies from W planes (virtual k rows kc0..kc0+31) ----
        {
            size_t idx = (size_t)(kc0 + b_row) * 16 + (unsigned)b_cg / 8;
            uint4 h0 = wH[idx], h1 = wH[idx + 1];
            uint4 l0 = wL[idx], l1 = wL[idx + 1];
            *(uint4*)&sBh[b_row][b_cg]     = h0;
            *(uint4*)&sBh[b_row][b_cg + 8] = h1;
            *(uint4*)&sBl[b_row][b_cg]     = l0;
            *(uint4*)&sBl[b_row][b_cg + 8] = l1;
        }
        __syncthreads();

        // ---- compute: 2 k16 steps ----
#pragma unroll
        for (int ks = 0; ks < 2; ++ks) {
            int k0 = ks * 16;
            uint32_t ah[2][4], al[2][4];
#pragma unroll
            for (int mf = 0; mf < 2; ++mf) {
                int ar = m_base + mf * 16 + frow;
                int ac = k0 + fcol;
                ldmx4(ah[mf], smem_u32(&sAh[ar][ac]));
                ldmx4(al[mf], smem_u32(&sAl[ar][ac]));
            }
#pragma unroll
            for (int ng = 0; ng < 4; ++ng) {
                int br = k0 + frow;
                int bc = n_base + ng * 16 + fcol;
                uint32_t bh[4], blo[4];
                ldmx4t(bh,  smem_u32(&sBh[br][bc]));
                ldmx4t(blo, smem_u32(&sBl[br][bc]));
#pragma unroll
                for (int mf = 0; mf < 2; ++mf) {
#pragma unroll
                    for (int h = 0; h < 2; ++h) {
                        float* c = acc[mf][ng * 2 + h];
                        mma16816(c, ah[mf], &bh[h * 2]);
                        mma16816(c, ah[mf], &blo[h * 2]);
                        mma16816(c, al[mf], &bh[h * 2]);
                    }
                }
            }
        }
    }

    // ---- epilogue: BN (+ Mish); out_sel 0 -> fp32 d_out, else h planes (bf16 hi/lo) ----
    uint32_t* hp = (out_sel == 1) ? (uint32_t*)g_h0_h4 : (uint32_t*)g_h1_h4;
    uint32_t* lp = (out_sel == 1) ? (uint32_t*)g_h0_l4 : (uint32_t*)g_h1_l4;
    int gid = lane >> 2;
    int tig = lane & 3;
#pragma unroll
    for (int mf = 0; mf < 2; ++mf) {
#pragma unroll
        for (int nf = 0; nf < 8; ++nf) {
            int cbase = n_base + nf * 8 + tig * 2;
            float sc0 = s_sc[cbase], sc1 = s_sc[cbase + 1];
            float of0 = s_off[cbase], of1 = s_off[cbase + 1];
#pragma unroll
            for (int h = 0; h < 2; ++h) {
                int r = row0 + m_base + mf * 16 + gid + h * 8;
                if (r >= N_NODES) continue;
                float v0 = acc[mf][nf][h * 2 + 0] * sc0 + of0;
                float v1 = acc[mf][nf][h * 2 + 1] * sc1 + of1;
                if (apply_mish) {
                    float sp0 = (v0 > 20.f) ? v0 : log1pf(expf(v0));
                    v0 = v0 * tanhf(sp0);
                    float sp1 = (v1 > 20.f) ? v1 : log1pf(expf(v1));
                    v1 = v1 * tanhf(sp1);
                }
                if (out_sel == 0) {
                    *(float2*)(out_ext + (size_t)r * C + cbase) = make_float2(v0, v1);
                } else {
                    uint32_t hw, lw;
                    split2(v0, v1, hw, lw);
                    size_t widx = (size_t)r * 64 + (unsigned)cbase / 2;
                    hp[widx] = hw;
                    lp[widx] = lw;
                }
            }
        }
    }
}

// ---------------- host launcher (graph-capturable: kernel launches only) ----------------
extern "C" void kernel_launch(void* const* d_in, const int* in_sizes, int n_in,
                              void* d_out, int out_size) {
    const float* x  = (const float*)d_in[0];
    const void*  ei = d_in[1];
    const float* Wl = (const float*)d_in[2];
    const float* bl = (const float*)d_in[3];
    const float* Wr = (const float*)d_in[4];
    const float* ga = (const float*)d_in[5];
    const float* be = (const float*)d_in[6];
    const float* rm = (const float*)d_in[7];
    const float* rv = (const float*)d_in[8];
    float* out = (float*)d_out;

    int E = in_sizes[1] / 2;

    int eb = (E + 255) / 256;
    int nb = (N_NODES + 255) / 256;
    int wb = (N_NODES * 32 + 255) / 256;
    int gb = (N_NODES + 127) / 128;
    int cwb = (3 * 2 * C * C + 255) / 256;
    int cxb = (int)(((size_t)N_NODES * C / 4 + 255) / 256);

    // ---- one-time conversions + CSR build ----
    detect_kernel<<<1, 1>>>(ei);
    convw_kernel<<<cwb, 256>>>(Wl, Wr);
    convx_kernel<<<cxb, 256>>>((const float4*)x);
    zero_deg_kernel<<<nb, 256>>>();
    hist_kernel<<<eb, 256>>>(ei, E);
    bsum_kernel<<<SCAN_NB, SCAN_B>>>();
    scan_boff_kernel<<<1, 32>>>();
    rowptr_kernel<<<SCAN_NB, SCAN_B>>>(E);
    fill_kernel<<<eb, 256>>>(ei, E);

    // layer 0: in = x, out = h0 planes
    gather_kernel<<<wb, 256>>>((const float4*)x, 0);
    sage_mma_kernel<<<gb, 256>>>(0, nullptr, 1, 0,
                                 bl + 0 * C, ga + 0 * C, be + 0 * C, rm + 0 * C, rv + 0 * C, 1);

    // layer 1: in = h0 planes, out = h1 planes
    gather_kernel<<<wb, 256>>>(nullptr, 1);
    sage_mma_kernel<<<gb, 256>>>(1, nullptr, 2, 1,
                                 bl + 1 * C, ga + 1 * C, be + 1 * C, rm + 1 * C, rv + 1 * C, 1);

    // layer 2: in = h1 planes, out = fp32 d_out, no Mish
    gather_kernel<<<wb, 256>>>(nullptr, 2);
    sage_mma_kernel<<<gb, 256>>>(2, out, 0, 2,
                                 bl + 2 * C, ga + 2 * C, be + 2 * C, rm + 2 * C, rv + 2 * C, 0);
}

// round 13
// speedup vs baseline: 1.6950x; 1.0091x over previous
#include <cuda_runtime.h>
#include <cuda_bf16.h>
#include <math.h>
#include <stdint.h>

#define N_NODES 100000
#define C 128
#define BN_EPS 1e-5f
#define MAX_E 1600000
#define SCAN_B 512
#define SCAN_NB ((N_NODES + SCAN_B - 1) / SCAN_B)   // 196
#define PLANE4 ((size_t)N_NODES * C / 8)            // uint4 count per bf16 plane

// ---------------- persistent device scratch (no allocations; 16B-aligned) ----------------
__device__ uint4 g_agg_h4[PLANE4], g_agg_l4[PLANE4];
__device__ uint4 g_x_h4[PLANE4],   g_x_l4[PLANE4];
__device__ uint4 g_h0_h4[PLANE4],  g_h0_l4[PLANE4];
__device__ uint4 g_h1_h4[PLANE4],  g_h1_l4[PLANE4];
__device__ uint4 g_w_h4[3 * 2 * C * C / 8], g_w_l4[3 * 2 * C * C / 8];  // [layer][k][n]
__device__ int    g_deg[N_NODES];
__device__ int    g_rowptr[N_NODES + 1];
__device__ int    g_cursor[N_NODES];
__device__ float  g_inv[N_NODES];
__device__ int    g_esrc[MAX_E];
__device__ int    g_boff[SCAN_NB + 1];
__device__ int    g_is64;

// ---------------- bf16 pack/unpack helpers ----------------
__device__ __forceinline__ float2 bf2f(uint32_t u) {
    return __bfloat1622float2(*reinterpret_cast<const __nv_bfloat162*>(&u));
}
__device__ __forceinline__ uint32_t packbf(__nv_bfloat16 a, __nv_bfloat16 b) {
    __nv_bfloat162 h; h.x = a; h.y = b;
    return *reinterpret_cast<uint32_t*>(&h);
}
__device__ __forceinline__ void split2(float v0, float v1, uint32_t& hw, uint32_t& lw) {
    __nv_bfloat16 h0 = __float2bfloat16(v0), h1 = __float2bfloat16(v1);
    __nv_bfloat16 l0 = __float2bfloat16(v0 - __bfloat162float(h0));
    __nv_bfloat16 l1 = __float2bfloat16(v1 - __bfloat162float(h1));
    hw = packbf(h0, h1);
    lw = packbf(l0, l1);
}

// ---------------- warp-MMA + cp.async helpers (sm_80+ PTX) ----------------
__device__ __forceinline__ uint32_t smem_u32(const void* p) {
    return (uint32_t)__cvta_generic_to_shared(p);
}
__device__ __forceinline__ void ldmx4(uint32_t r[4], uint32_t addr) {
    asm volatile("ldmatrix.sync.aligned.m8n8.x4.shared.b16 {%0,%1,%2,%3}, [%4];"
                 : "=r"(r[0]), "=r"(r[1]), "=r"(r[2]), "=r"(r[3]) : "r"(addr));
}
__device__ __forceinline__ void ldmx4t(uint32_t r[4], uint32_t addr) {
    asm volatile("ldmatrix.sync.aligned.m8n8.x4.trans.shared.b16 {%0,%1,%2,%3}, [%4];"
                 : "=r"(r[0]), "=r"(r[1]), "=r"(r[2]), "=r"(r[3]) : "r"(addr));
}
__device__ __forceinline__ void mma16816(float c[4], const uint32_t a[4], const uint32_t b[2]) {
    asm volatile("mma.sync.aligned.m16n8k16.row.col.f32.bf16.bf16.f32 "
                 "{%0,%1,%2,%3}, {%4,%5,%6,%7}, {%8,%9}, {%0,%1,%2,%3};"
                 : "+f"(c[0]), "+f"(c[1]), "+f"(c[2]), "+f"(c[3])
                 : "r"(a[0]), "r"(a[1]), "r"(a[2]), "r"(a[3]), "r"(b[0]), "r"(b[1]));
}
__device__ __forceinline__ void cp16(uint32_t dst, const void* src, int nbytes) {
    asm volatile("cp.async.cg.shared.global [%0], [%1], 16, %2;\n"
                 :: "r"(dst), "l"(src), "r"(nbytes));
}
__device__ __forceinline__ void cp_commit() { asm volatile("cp.async.commit_group;\n"); }
__device__ __forceinline__ void cp_wait0()  { asm volatile("cp.async.wait_group 0;\n"); }

// ---------------- detect edge_index dtype (int64 vs int32) ----------------
__global__ void detect_kernel(const void* __restrict__ ei) {
    const long long* p64 = (const long long*)ei;
    int ok = 1;
    for (int i = 0; i < 64; ++i) {
        long long v = p64[i];
        if (v < 0 || v >= N_NODES) { ok = 0; break; }
    }
    g_is64 = ok;
}

__device__ __forceinline__ int load_idx(const void* ei, size_t i) {
    return g_is64 ? (int)((const long long*)ei)[i] : ((const int*)ei)[i];
}

// ---------------- one-time conversions ----------------
__global__ void convw_kernel(const float* __restrict__ Wl, const float* __restrict__ Wr) {
    int i = blockIdx.x * blockDim.x + threadIdx.x;
    if (i >= 3 * 2 * C * C) return;
    int layer = i / (2 * C * C);
    int rem = i % (2 * C * C);
    int k = rem / C, n = rem % C;
    float v = (k < C) ? Wl[(size_t)layer * C * C + k * C + n]
                      : Wr[(size_t)layer * C * C + (k - C) * C + n];
    __nv_bfloat16 h = __float2bfloat16(v);
    ((__nv_bfloat16*)g_w_h4)[i] = h;
    ((__nv_bfloat16*)g_w_l4)[i] = __float2bfloat16(v - __bfloat162float(h));
}

__global__ void convx_kernel(const float4* __restrict__ x4) {
    size_t i = (size_t)blockIdx.x * blockDim.x + threadIdx.x;
    if (i >= (size_t)N_NODES * C / 4) return;
    float4 v = x4[i];
    uint2 hw, lw;
    split2(v.x, v.y, hw.x, lw.x);
    split2(v.z, v.w, hw.y, lw.y);
    ((uint2*)g_x_h4)[i] = hw;
    ((uint2*)g_x_l4)[i] = lw;
}

// ---------------- CSR build ----------------
__global__ void zero_deg_kernel() {
    int i = blockIdx.x * blockDim.x + threadIdx.x;
    if (i < N_NODES) g_deg[i] = 0;
}

__global__ void hist_kernel(const void* __restrict__ ei, int E) {
    int e = blockIdx.x * blockDim.x + threadIdx.x;
    if (e >= E) return;
    int d = load_idx(ei, (size_t)E + e);
    if ((unsigned)d < N_NODES) atomicAdd(&g_deg[d], 1);
}

__global__ void bsum_kernel() {
    __shared__ int sh[SCAN_B];
    int i = blockIdx.x * SCAN_B + threadIdx.x;
    sh[threadIdx.x] = (i < N_NODES) ? g_deg[i] : 0;
    __syncthreads();
    for (int s = SCAN_B / 2; s > 0; s >>= 1) {
        if (threadIdx.x < s) sh[threadIdx.x] += sh[threadIdx.x + s];
        __syncthreads();
    }
    if (threadIdx.x == 0) g_boff[blockIdx.x] = sh[0];
}

__global__ void scan_boff_kernel() {
    if (threadIdx.x == 0 && blockIdx.x == 0) {
        int acc = 0;
        for (int b = 0; b < SCAN_NB; ++b) {
            int v = g_boff[b];
            g_boff[b] = acc;
            acc += v;
        }
        g_boff[SCAN_NB] = acc;
    }
}

__global__ void rowptr_kernel(int E) {
    __shared__ int sh[SCAN_B];
    int i = blockIdx.x * SCAN_B + threadIdx.x;
    int d = (i < N_NODES) ? g_deg[i] : 0;
    sh[threadIdx.x] = d;
    __syncthreads();
    for (int s = 1; s < SCAN_B; s <<= 1) {
        int v = (threadIdx.x >= s) ? sh[threadIdx.x - s] : 0;
        __syncthreads();
        sh[threadIdx.x] += v;
        __syncthreads();
    }
    if (i < N_NODES) {
        int start = g_boff[blockIdx.x] + sh[threadIdx.x] - d;  // exclusive
        g_rowptr[i] = start;
        g_cursor[i] = start;
        g_inv[i] = 1.0f / fmaxf((float)d, 1.0f);
        if (i == N_NODES - 1) g_rowptr[N_NODES] = g_boff[SCAN_NB];
    }
}

__global__ void fill_kernel(const void* __restrict__ ei, int E) {
    int e = blockIdx.x * blockDim.x + threadIdx.x;
    if (e >= E) return;
    int s = load_idx(ei, e);
    int d = load_idx(ei, (size_t)E + e);
    if ((unsigned)s >= N_NODES || (unsigned)d >= N_NODES) return;
    int slot = atomicAdd(&g_cursor[d], 1);
    if (slot < MAX_E) g_esrc[slot] = s;
}

// ---------------- gather-aggregate: warp per node; writes mean as bf16 hi/lo planes -----
__global__ __launch_bounds__(256)
void gather_kernel(const float4* __restrict__ x_ext, int in_sel) {
    int warp = (blockIdx.x * blockDim.x + threadIdx.x) >> 5;
    int lane = threadIdx.x & 31;
    if (warp >= N_NODES) return;
    int beg = g_rowptr[warp];
    int end = g_rowptr[warp + 1];

    float4 a0 = make_float4(0.f, 0.f, 0.f, 0.f);
    float4 a1 = a0;

    if (in_sel == 0) {
        int e = beg;
        for (; e + 2 <= end; e += 2) {
            int s0 = g_esrc[e], s1 = g_esrc[e + 1];
            float4 v0 = x_ext[(size_t)s0 * 32 + lane];
            float4 v1 = x_ext[(size_t)s1 * 32 + lane];
            a0.x += v0.x; a0.y += v0.y; a0.z += v0.z; a0.w += v0.w;
            a1.x += v1.x; a1.y += v1.y; a1.z += v1.z; a1.w += v1.w;
        }
        for (; e < end; ++e) {
            int s0 = g_esrc[e];
            float4 v0 = x_ext[(size_t)s0 * 32 + lane];
            a0.x += v0.x; a0.y += v0.y; a0.z += v0.z; a0.w += v0.w;
        }
    } else {
        const uint2* hp = (in_sel == 1) ? (const uint2*)g_h0_h4 : (const uint2*)g_h1_h4;
        const uint2* lp = (in_sel == 1) ? (const uint2*)g_h0_l4 : (const uint2*)g_h1_l4;
        int e = beg;
        for (; e + 2 <= end; e += 2) {
            int s0 = g_esrc[e], s1 = g_esrc[e + 1];
            uint2 uh0 = hp[(size_t)s0 * 32 + lane];
            uint2 ul0 = lp[(size_t)s0 * 32 + lane];
            uint2 uh1 = hp[(size_t)s1 * 32 + lane];
            uint2 ul1 = lp[(size_t)s1 * 32 + lane];
            float2 h, l;
            h = bf2f(uh0.x); l = bf2f(ul0.x); a0.x += h.x + l.x; a0.y += h.y + l.y;
            h = bf2f(uh0.y); l = bf2f(ul0.y); a0.z += h.x + l.x; a0.w += h.y + l.y;
            h = bf2f(uh1.x); l = bf2f(ul1.x); a1.x += h.x + l.x; a1.y += h.y + l.y;
            h = bf2f(uh1.y); l = bf2f(ul1.y); a1.z += h.x + l.x; a1.w += h.y + l.y;
        }
        for (; e < end; ++e) {
            int s0 = g_esrc[e];
            uint2 uh0 = hp[(size_t)s0 * 32 + lane];
            uint2 ul0 = lp[(size_t)s0 * 32 + lane];
            float2 h, l;
            h = bf2f(uh0.x); l = bf2f(ul0.x); a0.x += h.x + l.x; a0.y += h.y + l.y;
            h = bf2f(uh0.y); l = bf2f(ul0.y); a0.z += h.x + l.x; a0.w += h.y + l.y;
        }
    }
    a0.x += a1.x; a0.y += a1.y; a0.z += a1.z; a0.w += a1.w;
    float iv = g_inv[warp];
    a0.x *= iv; a0.y *= iv; a0.z *= iv; a0.w *= iv;

    uint2 hw, lw;
    split2(a0.x, a0.y, hw.x, lw.x);
    split2(a0.z, a0.w, hw.y, lw.y);
    ((uint2*)g_agg_h4)[(size_t)warp * 32 + lane] = hw;
    ((uint2*)g_agg_l4)[(size_t)warp * 32 + lane] = lw;
}

// ---------------- tensor-core GEMM: cp.async double-buffered, pure-copy loader -----------
// D += Ah@Wh + Ah@Wl + Al@Wh. CTA 256 thr / 8 warps, 128x128 tile, K=256 in 8 chunks of 32.
// Dynamic smem layout (bytes), double-buffered:
//   AH: 128 rows x 80B   (APAD=40 bf16)   = 10240
//   AL: +10240
//   BH: 32 rows x 272B   (BPAD=136 bf16)  = 8704 at +20480
//   BL: +29184
//   buffer stride 37888; two buffers = 75776 total.
#define A_STRIDE 80
#define B_STRIDE 272
#define OFF_AL 10240
#define OFF_BH 20480
#define OFF_BL 29184
#define BUF_STRIDE 37888
__global__ __launch_bounds__(256)
void sage_mma_kernel(int in_sel, float* __restrict__ out_ext, int out_sel, int layer,
                     const float* __restrict__ bl,
                     const float* __restrict__ gamma, const float* __restrict__ beta,
                     const float* __restrict__ rmean, const float* __restrict__ rvar,
                     int apply_mish) {
    const uint4* hinH = (in_sel == 0) ? g_x_h4 : (in_sel == 1 ? g_h0_h4 : g_h1_h4);
    const uint4* hinL = (in_sel == 0) ? g_x_l4 : (in_sel == 1 ? g_h0_l4 : g_h1_l4);

    extern __shared__ __align__(16) unsigned char dyn[];
    uint32_t sbase = smem_u32(dyn);

    __shared__ float s_sc[128];
    __shared__ float s_off[128];

    int t = threadIdx.x;
    int wid = t >> 5;
    int lane = t & 31;
    int row0 = blockIdx.x * 128;

    if (t < 128) {
        float sc = gamma[t] * rsqrtf(rvar[t] + BN_EPS);
        s_sc[t] = sc;
        s_off[t] = (bl[t] - rmean[t]) * sc + beta[t];
    }

    int warp_m = wid & 3;
    int warp_n = wid >> 2;
    int m_base = warp_m * 32;
    int n_base = warp_n * 64;

    float acc[2][8][4];
#pragma unroll
    for (int i = 0; i < 2; ++i)
#pragma unroll
        for (int j = 0; j < 8; ++j)
#pragma unroll
            for (int q = 0; q < 4; ++q) acc[i][j][q] = 0.f;

    int a_row = t >> 1;            // 0..127
    int a_cg  = (t & 1) * 16;      // col group (bf16)
    int b_row = t >> 3;            // 0..31 (k)
    int b_cg  = (t & 7) * 16;

    const uint4* wH = g_w_h4 + (size_t)layer * (2 * C * C / 8);
    const uint4* wL = g_w_l4 + (size_t)layer * (2 * C * C / 8);

    int lg = lane >> 3;
    int lr = lane & 7;
    int frow = lr + (lg & 1) * 8;
    int fcol = (lg >> 1) * 8;

    int r_a = row0 + a_row;
    int a_ok = (r_a < N_NODES) ? 16 : 0;
    int r_ac = (r_a < N_NODES) ? r_a : 0;

    // issue async copy of chunk `ck` into buffer `buf`
    auto cp_tile = [&](int ck, int buf) {
        int kc0 = ck * 32;
        bool isAgg = (kc0 < C);
        const uint4* AH = isAgg ? g_agg_h4 : hinH;
        const uint4* AL = isAgg ? g_agg_l4 : hinL;
        int koff = isAgg ? kc0 : (kc0 - C);
        uint32_t bb = sbase + (uint32_t)(buf * BUF_STRIDE);

        size_t aidx = (size_t)r_ac * 16 + (unsigned)(koff + a_cg) / 8;
        uint32_t adst = bb + (uint32_t)(a_row * A_STRIDE + a_cg * 2);
        cp16(adst,          AH + aidx,     a_ok);
        cp16(adst + 16,     AH + aidx + 1, a_ok);
        cp16(adst + OFF_AL,      AL + aidx,     a_ok);
        cp16(adst + OFF_AL + 16, AL + aidx + 1, a_ok);

        size_t bidx = (size_t)(kc0 + b_row) * 16 + (unsigned)b_cg / 8;
        uint32_t bdst = bb + (uint32_t)(OFF_BH + b_row * B_STRIDE + b_cg * 2);
        cp16(bdst,      wH + bidx,     16);
        cp16(bdst + 16, wH + bidx + 1, 16);
        cp16(bdst + (OFF_BL - OFF_BH),      wL + bidx,     16);
        cp16(bdst + (OFF_BL - OFF_BH) + 16, wL + bidx + 1, 16);
        cp_commit();
    };

    cp_tile(0, 0);
    cp_wait0();
    __syncthreads();

    for (int ck = 0; ck < 8; ++ck) {
        int cur = ck & 1;
        bool have_next = (ck + 1 < 8);
        if (have_next) cp_tile(ck + 1, cur ^ 1);   // overlaps compute below

        uint32_t bb = sbase + (uint32_t)(cur * BUF_STRIDE);

#pragma unroll
        for (int ks = 0; ks < 2; ++ks) {
            int k0 = ks * 16;
            uint32_t ah[2][4], al[2][4];
#pragma unroll
            for (int mf = 0; mf < 2; ++mf) {
                int ar = m_base + mf * 16 + frow;
                int ac = k0 + fcol;
                uint32_t aaddr = bb + (uint32_t)(ar * A_STRIDE + ac * 2);
                ldmx4(ah[mf], aaddr);
                ldmx4(al[mf], aaddr + OFF_AL);
            }
#pragma unroll
            for (int ng = 0; ng < 4; ++ng) {
                int br = k0 + frow;
                int bc = n_base + ng * 16 + fcol;
                uint32_t baddr = bb + (uint32_t)(OFF_BH + br * B_STRIDE + bc * 2);
                uint32_t bh[4], blo[4];
                ldmx4t(bh,  baddr);
                ldmx4t(blo, baddr + (OFF_BL - OFF_BH));
#pragma unroll
                for (int mf = 0; mf < 2; ++mf) {
#pragma unroll
                    for (int h = 0; h < 2; ++h) {
                        float* c = acc[mf][ng * 2 + h];
                        mma16816(c, ah[mf], &bh[h * 2]);
                        mma16816(c, ah[mf], &blo[h * 2]);
                        mma16816(c, al[mf], &bh[h * 2]);
                    }
                }
            }
        }

        if (have_next) {
            cp_wait0();        // next chunk landed
            __syncthreads();   // all warps done reading `cur`
        }
    }

    // ---- epilogue: BN (+ Mish); out_sel 0 -> fp32 d_out, else h planes (bf16 hi/lo) ----
    uint32_t* hp = (out_sel == 1) ? (uint32_t*)g_h0_h4 : (uint32_t*)g_h1_h4;
    uint32_t* lp = (out_sel == 1) ? (uint32_t*)g_h0_l4 : (uint32_t*)g_h1_l4;
    int gid = lane >> 2;
    int tig = lane & 3;
#pragma unroll
    for (int mf = 0; mf < 2; ++mf) {
#pragma unroll
        for (int nf = 0; nf < 8; ++nf) {
            int cbase = n_base + nf * 8 + tig * 2;
            float sc0 = s_sc[cbase], sc1 = s_sc[cbase + 1];
            float of0 = s_off[cbase], of1 = s_off[cbase + 1];
#pragma unroll
            for (int h = 0; h < 2; ++h) {
                int r = row0 + m_base + mf * 16 + gid + h * 8;
                if (r >= N_NODES) continue;
                float v0 = acc[mf][nf][h * 2 + 0] * sc0 + of0;
                float v1 = acc[mf][nf][h * 2 + 1] * sc1 + of1;
                if (apply_mish) {
                    float sp0 = (v0 > 20.f) ? v0 : log1pf(expf(v0));
                    v0 = v0 * tanhf(sp0);
                    float sp1 = (v1 > 20.f) ? v1 : log1pf(expf(v1));
                    v1 = v1 * tanhf(sp1);
                }
                if (out_sel == 0) {
                    *(float2*)(out_ext + (size_t)r * C + cbase) = make_float2(v0, v1);
                } else {
                    uint32_t hw, lw;
                    split2(v0, v1, hw, lw);
                    size_t widx = (size_t)r * 64 + (unsigned)cbase / 2;
                    hp[widx] = hw;
                    lp[widx] = lw;
                }
            }
        }
    }
}

// ---------------- host launcher (graph-capturable: kernel launches only) ----------------
extern "C" void kernel_launch(void* const* d_in, const int* in_sizes, int n_in,
                              void* d_out, int out_size) {
    const float* x  = (const float*)d_in[0];
    const void*  ei = d_in[1];
    const float* Wl = (const float*)d_in[2];
    const float* bl = (const float*)d_in[3];
    const float* Wr = (const float*)d_in[4];
    const float* ga = (const float*)d_in[5];
    const float* be = (const float*)d_in[6];
    const float* rm = (const float*)d_in[7];
    const float* rv = (const float*)d_in[8];
    float* out = (float*)d_out;

    int E = in_sizes[1] / 2;

    int eb = (E + 255) / 256;
    int nb = (N_NODES + 255) / 256;
    int wb = (N_NODES * 32 + 255) / 256;
    int gb = (N_NODES + 127) / 128;
    int cwb = (3 * 2 * C * C + 255) / 256;
    int cxb = (int)(((size_t)N_NODES * C / 4 + 255) / 256);
    int dsm = 2 * BUF_STRIDE;   // 75776 B dynamic smem

    cudaFuncSetAttribute(sage_mma_kernel, cudaFuncAttributeMaxDynamicSharedMemorySize, dsm);

    // ---- one-time conversions + CSR build ----
    detect_kernel<<<1, 1>>>(ei);
    convw_kernel<<<cwb, 256>>>(Wl, Wr);
    convx_kernel<<<cxb, 256>>>((const float4*)x);
    zero_deg_kernel<<<nb, 256>>>();
    hist_kernel<<<eb, 256>>>(ei, E);
    bsum_kernel<<<SCAN_NB, SCAN_B>>>();
    scan_boff_kernel<<<1, 32>>>();
    rowptr_kernel<<<SCAN_NB, SCAN_B>>>(E);
    fill_kernel<<<eb, 256>>>(ei, E);

    // layer 0: in = x, out = h0 planes
    gather_kernel<<<wb, 256>>>((const float4*)x, 0);
    sage_mma_kernel<<<gb, 256, dsm>>>(0, nullptr, 1, 0,
                                      bl + 0 * C, ga + 0 * C, be + 0 * C, rm + 0 * C, rv + 0 * C, 1);

    // layer 1: in = h0 planes, out = h1 planes
    gather_kernel<<<wb, 256>>>(nullptr, 1);
    sage_mma_kernel<<<gb, 256, dsm>>>(1, nullptr, 2, 1,
                                      bl + 1 * C, ga + 1 * C, be + 1 * C, rm + 1 * C, rv + 1 * C, 1);

    // layer 2: in = h1 planes, out = fp32 d_out, no Mish
    gather_kernel<<<wb, 256>>>(nullptr, 2);
    sage_mma_kernel<<<gb, 256, dsm>>>(2, out, 0, 2,
                                      bl + 2 * C, ga + 2 * C, be + 2 * C, rm + 2 * C, rv + 2 * C, 0);
}

// round 15
// speedup vs baseline: 1.7339x; 1.0229x over previous
#include <cuda_runtime.h>
#include <cuda_bf16.h>
#include <math.h>
#include <stdint.h>

#define N_NODES 100000
#define C 128
#define BN_EPS 1e-5f
#define MAX_E 1600000
#define SCAN_B 512
#define SCAN_NB ((N_NODES + SCAN_B - 1) / SCAN_B)   // 196
#define PLANE4 ((size_t)N_NODES * C / 8)            // uint4 count per bf16 plane

// ---------------- persistent device scratch (no allocations; 16B-aligned) ----------------
__device__ uint4 g_agg_h4[PLANE4], g_agg_l4[PLANE4];
__device__ uint4 g_x_h4[PLANE4],   g_x_l4[PLANE4];
__device__ uint4 g_h0_h4[PLANE4],  g_h0_l4[PLANE4];
__device__ uint4 g_h1_h4[PLANE4],  g_h1_l4[PLANE4];
__device__ uint4 g_w_h4[3 * 2 * C * C / 8], g_w_l4[3 * 2 * C * C / 8];  // [layer][k][n]
__device__ int    g_deg[N_NODES];
__device__ int    g_rowptr[N_NODES];
__device__ int    g_cursor[N_NODES];
__device__ float  g_inv[N_NODES];
__device__ int    g_esrc[MAX_E];
__device__ int    g_total;
__device__ int    g_is64;

// ---------------- bf16 pack/unpack helpers ----------------
__device__ __forceinline__ float2 bf2f(uint32_t u) {
    return __bfloat1622float2(*reinterpret_cast<const __nv_bfloat162*>(&u));
}
__device__ __forceinline__ uint32_t packbf(__nv_bfloat16 a, __nv_bfloat16 b) {
    __nv_bfloat162 h; h.x = a; h.y = b;
    return *reinterpret_cast<uint32_t*>(&h);
}
__device__ __forceinline__ void split2(float v0, float v1, uint32_t& hw, uint32_t& lw) {
    __nv_bfloat16 h0 = __float2bfloat16(v0), h1 = __float2bfloat16(v1);
    __nv_bfloat16 l0 = __float2bfloat16(v0 - __bfloat162float(h0));
    __nv_bfloat16 l1 = __float2bfloat16(v1 - __bfloat162float(h1));
    hw = packbf(h0, h1);
    lw = packbf(l0, l1);
}

// ---------------- warp-MMA + cp.async helpers (sm_80+ PTX) ----------------
__device__ __forceinline__ uint32_t smem_u32(const void* p) {
    return (uint32_t)__cvta_generic_to_shared(p);
}
__device__ __forceinline__ void ldmx4(uint32_t r[4], uint32_t addr) {
    asm volatile("ldmatrix.sync.aligned.m8n8.x4.shared.b16 {%0,%1,%2,%3}, [%4];"
                 : "=r"(r[0]), "=r"(r[1]), "=r"(r[2]), "=r"(r[3]) : "r"(addr));
}
__device__ __forceinline__ void ldmx4t(uint32_t r[4], uint32_t addr) {
    asm volatile("ldmatrix.sync.aligned.m8n8.x4.trans.shared.b16 {%0,%1,%2,%3}, [%4];"
                 : "=r"(r[0]), "=r"(r[1]), "=r"(r[2]), "=r"(r[3]) : "r"(addr));
}
__device__ __forceinline__ void mma16816(float c[4], const uint32_t a[4], const uint32_t b[2]) {
    asm volatile("mma.sync.aligned.m16n8k16.row.col.f32.bf16.bf16.f32 "
                 "{%0,%1,%2,%3}, {%4,%5,%6,%7}, {%8,%9}, {%0,%1,%2,%3};"
                 : "+f"(c[0]), "+f"(c[1]), "+f"(c[2]), "+f"(c[3])
                 : "r"(a[0]), "r"(a[1]), "r"(a[2]), "r"(a[3]), "r"(b[0]), "r"(b[1]));
}
__device__ __forceinline__ void cp16(uint32_t dst, const void* src, int nbytes) {
    asm volatile("cp.async.cg.shared.global [%0], [%1], 16, %2;\n"
                 :: "r"(dst), "l"(src), "r"(nbytes));
}
__device__ __forceinline__ void cp_commit() { asm volatile("cp.async.commit_group;\n"); }
__device__ __forceinline__ void cp_wait0()  { asm volatile("cp.async.wait_group 0;\n"); }

__device__ __forceinline__ int load_idx(const void* ei, size_t i) {
    return g_is64 ? (int)((const long long*)ei)[i] : ((const int*)ei)[i];
}

// ---------------- prep: detect dtype + zero deg/total + convert W and x to planes --------
__global__ void prep_kernel(const void* __restrict__ ei,
                            const float* __restrict__ Wl, const float* __restrict__ Wr,
                            const float4* __restrict__ x4) {
    size_t gid = (size_t)blockIdx.x * blockDim.x + threadIdx.x;

    if (blockIdx.x == 0) {
        __shared__ int ok;
        if (threadIdx.x == 0) ok = 1;
        __syncthreads();
        if (threadIdx.x < 64) {
            long long v = ((const long long*)ei)[threadIdx.x];
            if (v < 0 || v >= N_NODES) ok = 0;   // benign race: all writers write 0
        }
        __syncthreads();
        if (threadIdx.x == 0) { g_is64 = ok; g_total = 0; }
    }

    if (gid < N_NODES) g_deg[gid] = 0;

    if (gid < 3 * 2 * C * C) {
        int i = (int)gid;
        int layer = i / (2 * C * C);
        int rem = i % (2 * C * C);
        int k = rem / C, n = rem % C;
        float v = (k < C) ? Wl[(size_t)layer * C * C + k * C + n]
                          : Wr[(size_t)layer * C * C + (k - C) * C + n];
        __nv_bfloat16 h = __float2bfloat16(v);
        ((__nv_bfloat16*)g_w_h4)[i] = h;
        ((__nv_bfloat16*)g_w_l4)[i] = __float2bfloat16(v - __bfloat162float(h));
    }

    if (gid < (size_t)N_NODES * C / 4) {
        float4 v = x4[gid];
        uint2 hw, lw;
        split2(v.x, v.y, hw.x, lw.x);
        split2(v.z, v.w, hw.y, lw.y);
        ((uint2*)g_x_h4)[gid] = hw;
        ((uint2*)g_x_l4)[gid] = lw;
    }
}

// ---------------- CSR build ----------------
__global__ void hist_kernel(const void* __restrict__ ei, int E) {
    int e = blockIdx.x * blockDim.x + threadIdx.x;
    if (e >= E) return;
    int d = load_idx(ei, (size_t)E + e);
    if ((unsigned)d < N_NODES) atomicAdd(&g_deg[d], 1);
}

// block-local scan + atomic block base (bucket order nondeterministic; ranges consistent)
__global__ void rowptr_kernel(int E) {
    __shared__ int sh[SCAN_B];
    __shared__ int base;
    int i = blockIdx.x * SCAN_B + threadIdx.x;
    int d = (i < N_NODES) ? g_deg[i] : 0;
    sh[threadIdx.x] = d;
    __syncthreads();
    for (int s = 1; s < SCAN_B; s <<= 1) {
        int v = (threadIdx.x >= s) ? sh[threadIdx.x - s] : 0;
        __syncthreads();
        sh[threadIdx.x] += v;
        __syncthreads();
    }
    if (threadIdx.x == SCAN_B - 1) base = atomicAdd(&g_total, sh[SCAN_B - 1]);
    __syncthreads();
    if (i < N_NODES) {
        int start = base + sh[threadIdx.x] - d;   // exclusive within block + block base
        g_rowptr[i] = start;
        g_cursor[i] = start;
        g_inv[i] = 1.0f / fmaxf((float)d, 1.0f);
    }
}

__global__ void fill_kernel(const void* __restrict__ ei, int E) {
    int e = blockIdx.x * blockDim.x + threadIdx.x;
    if (e >= E) return;
    int s = load_idx(ei, e);
    int d = load_idx(ei, (size_t)E + e);
    if ((unsigned)s >= N_NODES || (unsigned)d >= N_NODES) return;
    int slot = atomicAdd(&g_cursor[d], 1);
    if (slot < MAX_E) g_esrc[slot] = s;
}

// ---------------- gather-aggregate: warp per node; writes mean as bf16 hi/lo planes -----
__global__ __launch_bounds__(256)
void gather_kernel(const float4* __restrict__ x_ext, int in_sel) {
    int warp = (blockIdx.x * blockDim.x + threadIdx.x) >> 5;
    int lane = threadIdx.x & 31;
    if (warp >= N_NODES) return;
    int beg = g_rowptr[warp];
    int end = beg + g_deg[warp];

    float4 a0 = make_float4(0.f, 0.f, 0.f, 0.f);
    float4 a1 = a0;

    if (in_sel == 0) {
        int e = beg;
        for (; e + 2 <= end; e += 2) {
            int s0 = g_esrc[e], s1 = g_esrc[e + 1];
            float4 v0 = x_ext[(size_t)s0 * 32 + lane];
            float4 v1 = x_ext[(size_t)s1 * 32 + lane];
            a0.x += v0.x; a0.y += v0.y; a0.z += v0.z; a0.w += v0.w;
            a1.x += v1.x; a1.y += v1.y; a1.z += v1.z; a1.w += v1.w;
        }
        for (; e < end; ++e) {
            int s0 = g_esrc[e];
            float4 v0 = x_ext[(size_t)s0 * 32 + lane];
            a0.x += v0.x; a0.y += v0.y; a0.z += v0.z; a0.w += v0.w;
        }
    } else {
        const uint2* hp = (in_sel == 1) ? (const uint2*)g_h0_h4 : (const uint2*)g_h1_h4;
        const uint2* lp = (in_sel == 1) ? (const uint2*)g_h0_l4 : (const uint2*)g_h1_l4;
        int e = beg;
        for (; e + 2 <= end; e += 2) {
            int s0 = g_esrc[e], s1 = g_esrc[e + 1];
            uint2 uh0 = hp[(size_t)s0 * 32 + lane];
            uint2 ul0 = lp[(size_t)s0 * 32 + lane];
            uint2 uh1 = hp[(size_t)s1 * 32 + lane];
            uint2 ul1 = lp[(size_t)s1 * 32 + lane];
            float2 h, l;
            h = bf2f(uh0.x); l = bf2f(ul0.x); a0.x += h.x + l.x; a0.y += h.y + l.y;
            h = bf2f(uh0.y); l = bf2f(ul0.y); a0.z += h.x + l.x; a0.w += h.y + l.y;
            h = bf2f(uh1.x); l = bf2f(ul1.x); a1.x += h.x + l.x; a1.y += h.y + l.y;
            h = bf2f(uh1.y); l = bf2f(ul1.y); a1.z += h.x + l.x; a1.w += h.y + l.y;
        }
        for (; e < end; ++e) {
            int s0 = g_esrc[e];
            uint2 uh0 = hp[(size_t)s0 * 32 + lane];
            uint2 ul0 = lp[(size_t)s0 * 32 + lane];
            float2 h, l;
            h = bf2f(uh0.x); l = bf2f(ul0.x); a0.x += h.x + l.x; a0.y += h.y + l.y;
            h = bf2f(uh0.y); l = bf2f(ul0.y); a0.z += h.x + l.x; a0.w += h.y + l.y;
        }
    }
    a0.x += a1.x; a0.y += a1.y; a0.z += a1.z; a0.w += a1.w;
    float iv = g_inv[warp];
    a0.x *= iv; a0.y *= iv; a0.z *= iv; a0.w *= iv;

    uint2 hw, lw;
    split2(a0.x, a0.y, hw.x, lw.x);
    split2(a0.z, a0.w, hw.y, lw.y);
    ((uint2*)g_agg_h4)[(size_t)warp * 32 + lane] = hw;
    ((uint2*)g_agg_l4)[(size_t)warp * 32 + lane] = lw;
}

// ---------------- tensor-core GEMM: cp.async double-buffered, pure-copy loader -----------
// D += Ah@Wh + Ah@Wl + Al@Wh. CTA 256 thr / 8 warps, 128x128 tile, K=256 in 8 chunks of 32.
#define A_STRIDE 80
#define B_STRIDE 272
#define OFF_AL 10240
#define OFF_BH 20480
#define OFF_BL 29184
#define BUF_STRIDE 37888
__global__ __launch_bounds__(256)
void sage_mma_kernel(int in_sel, float* __restrict__ out_ext, int out_sel, int layer,
                     const float* __restrict__ bl,
                     const float* __restrict__ gamma, const float* __restrict__ beta,
                     const float* __restrict__ rmean, const float* __restrict__ rvar,
                     int apply_mish) {
    const uint4* hinH = (in_sel == 0) ? g_x_h4 : (in_sel == 1 ? g_h0_h4 : g_h1_h4);
    const uint4* hinL = (in_sel == 0) ? g_x_l4 : (in_sel == 1 ? g_h0_l4 : g_h1_l4);

    extern __shared__ __align__(16) unsigned char dyn[];
    uint32_t sbase = smem_u32(dyn);

    __shared__ float s_sc[128];
    __shared__ float s_off[128];

    int t = threadIdx.x;
    int wid = t >> 5;
    int lane = t & 31;
    int row0 = blockIdx.x * 128;

    if (t < 128) {
        float sc = gamma[t] * rsqrtf(rvar[t] + BN_EPS);
        s_sc[t] = sc;
        s_off[t] = (bl[t] - rmean[t]) * sc + beta[t];
    }

    int warp_m = wid & 3;
    int warp_n = wid >> 2;
    int m_base = warp_m * 32;
    int n_base = warp_n * 64;

    float acc[2][8][4];
#pragma unroll
    for (int i = 0; i < 2; ++i)
#pragma unroll
        for (int j = 0; j < 8; ++j)
#pragma unroll
            for (int q = 0; q < 4; ++q) acc[i][j][q] = 0.f;

    int a_row = t >> 1;
    int a_cg  = (t & 1) * 16;
    int b_row = t >> 3;
    int b_cg  = (t & 7) * 16;

    const uint4* wH = g_w_h4 + (size_t)layer * (2 * C * C / 8);
    const uint4* wL = g_w_l4 + (size_t)layer * (2 * C * C / 8);

    int lg = lane >> 3;
    int lr = lane & 7;
    int frow = lr + (lg & 1) * 8;
    int fcol = (lg >> 1) * 8;

    int r_a = row0 + a_row;
    int a_ok = (r_a < N_NODES) ? 16 : 0;
    int r_ac = (r_a < N_NODES) ? r_a : 0;

    auto cp_tile = [&](int ck, int buf) {
        int kc0 = ck * 32;
        bool isAgg = (kc0 < C);
        const uint4* AH = isAgg ? g_agg_h4 : hinH;
        const uint4* AL = isAgg ? g_agg_l4 : hinL;
        int koff = isAgg ? kc0 : (kc0 - C);
        uint32_t bb = sbase + (uint32_t)(buf * BUF_STRIDE);

        size_t aidx = (size_t)r_ac * 16 + (unsigned)(koff + a_cg) / 8;
        uint32_t adst = bb + (uint32_t)(a_row * A_STRIDE + a_cg * 2);
        cp16(adst,          AH + aidx,     a_ok);
        cp16(adst + 16,     AH + aidx + 1, a_ok);
        cp16(adst + OFF_AL,      AL + aidx,     a_ok);
        cp16(adst + OFF_AL + 16, AL + aidx + 1, a_ok);

        size_t bidx = (size_t)(kc0 + b_row) * 16 + (unsigned)b_cg / 8;
        uint32_t bdst = bb + (uint32_t)(OFF_BH + b_row * B_STRIDE + b_cg * 2);
        cp16(bdst,      wH + bidx,     16);
        cp16(bdst + 16, wH + bidx + 1, 16);
        cp16(bdst + (OFF_BL - OFF_BH),      wL + bidx,     16);
        cp16(bdst + (OFF_BL - OFF_BH) + 16, wL + bidx + 1, 16);
        cp_commit();
    };

    cp_tile(0, 0);
    cp_wait0();
    __syncthreads();

    for (int ck = 0; ck < 8; ++ck) {
        int cur = ck & 1;
        bool have_next = (ck + 1 < 8);
        if (have_next) cp_tile(ck + 1, cur ^ 1);

        uint32_t bb = sbase + (uint32_t)(cur * BUF_STRIDE);

#pragma unroll
        for (int ks = 0; ks < 2; ++ks) {
            int k0 = ks * 16;
            uint32_t ah[2][4], al[2][4];
#pragma unroll
            for (int mf = 0; mf < 2; ++mf) {
                int ar = m_base + mf * 16 + frow;
                int ac = k0 + fcol;
                uint32_t aaddr = bb + (uint32_t)(ar * A_STRIDE + ac * 2);
                ldmx4(ah[mf], aaddr);
                ldmx4(al[mf], aaddr + OFF_AL);
            }
#pragma unroll
            for (int ng = 0; ng < 4; ++ng) {
                int br = k0 + frow;
                int bc = n_base + ng * 16 + fcol;
                uint32_t baddr = bb + (uint32_t)(OFF_BH + br * B_STRIDE + bc * 2);
                uint32_t bh[4], blo[4];
                ldmx4t(bh,  baddr);
                ldmx4t(blo, baddr + (OFF_BL - OFF_BH));
#pragma unroll
                for (int mf = 0; mf < 2; ++mf) {
#pragma unroll
                    for (int h = 0; h < 2; ++h) {
                        float* c = acc[mf][ng * 2 + h];
                        mma16816(c, ah[mf], &bh[h * 2]);
                        mma16816(c, ah[mf], &blo[h * 2]);
                        mma16816(c, al[mf], &bh[h * 2]);
                    }
                }
            }
        }

        if (have_next) {
            cp_wait0();
            __syncthreads();
        }
    }

    // ---- epilogue: BN (+ Mish); out_sel 0 -> fp32 d_out, else h planes (bf16 hi/lo) ----
    uint32_t* hp = (out_sel == 1) ? (uint32_t*)g_h0_h4 : (uint32_t*)g_h1_h4;
    uint32_t* lp = (out_sel == 1) ? (uint32_t*)g_h0_l4 : (uint32_t*)g_h1_l4;
    int gid = lane >> 2;
    int tig = lane & 3;
#pragma unroll
    for (int mf = 0; mf < 2; ++mf) {
#pragma unroll
        for (int nf = 0; nf < 8; ++nf) {
            int cbase = n_base + nf * 8 + tig * 2;
            float sc0 = s_sc[cbase], sc1 = s_sc[cbase + 1];
            float of0 = s_off[cbase], of1 = s_off[cbase + 1];
#pragma unroll
            for (int h = 0; h < 2; ++h) {
                int r = row0 + m_base + mf * 16 + gid + h * 8;
                if (r >= N_NODES) continue;
                float v0 = acc[mf][nf][h * 2 + 0] * sc0 + of0;
                float v1 = acc[mf][nf][h * 2 + 1] * sc1 + of1;
                if (apply_mish) {
                    float sp0 = (v0 > 20.f) ? v0 : log1pf(expf(v0));
                    v0 = v0 * tanhf(sp0);
                    float sp1 = (v1 > 20.f) ? v1 : log1pf(expf(v1));
                    v1 = v1 * tanhf(sp1);
                }
                if (out_sel == 0) {
                    *(float2*)(out_ext + (size_t)r * C + cbase) = make_float2(v0, v1);
                } else {
                    uint32_t hw, lw;
                    split2(v0, v1, hw, lw);
                    size_t widx = (size_t)r * 64 + (unsigned)cbase / 2;
                    hp[widx] = hw;
                    lp[widx] = lw;
                }
            }
        }
    }
}

// ---------------- host launcher (graph-capturable: kernel launches only) ----------------
extern "C" void kernel_launch(void* const* d_in, const int* in_sizes, int n_in,
                              void* d_out, int out_size) {
    const float* x  = (const float*)d_in[0];
    const void*  ei = d_in[1];
    const float* Wl = (const float*)d_in[2];
    const float* bl = (const float*)d_in[3];
    const float* Wr = (const float*)d_in[4];
    const float* ga = (const float*)d_in[5];
    const float* be = (const float*)d_in[6];
    const float* rm = (const float*)d_in[7];
    const float* rv = (const float*)d_in[8];
    float* out = (float*)d_out;

    int E = in_sizes[1] / 2;

    int eb = (E + 255) / 256;
    int wb = (N_NODES * 32 + 255) / 256;
    int gb = (N_NODES + 127) / 128;
    int pb = (int)(((size_t)N_NODES * C / 4 + 255) / 256);   // covers deg/convw/convx
    int dsm = 2 * BUF_STRIDE;   // 75776 B dynamic smem

    cudaFuncSetAttribute(sage_mma_kernel, cudaFuncAttributeMaxDynamicSharedMemorySize, dsm);

    // ---- 5 launches before gemm0 so ncu (-s 5 -c 1) captures sage_mma_kernel ----
    prep_kernel<<<pb, 256>>>(ei, Wl, Wr, (const float4*)x);     // 1
    hist_kernel<<<eb, 256>>>(ei, E);                             // 2
    rowptr_kernel<<<SCAN_NB, SCAN_B>>>(E);                       // 3
    fill_kernel<<<eb, 256>>>(ei, E);                             // 4

    // layer 0
    gather_kernel<<<wb, 256>>>((const float4*)x, 0);             // 5
    sage_mma_kernel<<<gb, 256, dsm>>>(0, nullptr, 1, 0,          // 6  <- profiled
                                      bl + 0 * C, ga + 0 * C, be + 0 * C, rm + 0 * C, rv + 0 * C, 1);
    // layer 1
    gather_kernel<<<wb, 256>>>(nullptr, 1);
    sage_mma_kernel<<<gb, 256, dsm>>>(1, nullptr, 2, 1,
                                      bl + 1 * C, ga + 1 * C, be + 1 * C, rm + 1 * C, rv + 1 * C, 1);
    // layer 2
    gather_kernel<<<wb, 256>>>(nullptr, 2);
    sage_mma_kernel<<<gb, 256, dsm>>>(2, out, 0, 2,
                                      bl + 2 * C, ga + 2 * C, be + 2 * C, rm + 2 * C, rv + 2 * C, 0);
}